// round 1
// baseline (speedup 1.0000x reference)
#include <cuda_runtime.h>
#include <math.h>

#define HID   4096
#define NH    32
#define HD    128
#define HALF  64
#define BB    2
#define SS    2048
#define THID  12288
#define SCALING 0.08838834764831845f   // 128^-0.5

// Scratch (alloc-free): QKV buffer and attention output buffer.
__device__ float g_qkv [(size_t)BB * SS * THID];   // [B*S, 3*HID] : [q | k | v]
__device__ float g_attn[(size_t)BB * SS * HID];    // [B*S, HID]   (b,s,h,d)

// ---------------------------------------------------------------------------
// GEMM: C[M,N] = A[M,K] @ B[K,N], all row-major fp32. M,N % 128 == 0, K % 16 == 0.
// 256 threads, 128x128 block tile, 16 k-tile, 8x8 per-thread register tile.
// ---------------------------------------------------------------------------
__global__ __launch_bounds__(256) void gemm128(const float* __restrict__ A,
                                               const float* __restrict__ B,
                                               float* __restrict__ C,
                                               int M, int N, int K) {
    __shared__ float As[16][128];   // transposed: As[k][m]
    __shared__ float Bs[16][128];   // Bs[k][n]

    const int tid = threadIdx.x;
    const int n0 = blockIdx.x * 128;
    const int m0 = blockIdx.y * 128;
    const int tm = (tid / 16) * 8;
    const int tn = (tid % 16) * 8;

    float acc[8][8];
#pragma unroll
    for (int i = 0; i < 8; i++)
#pragma unroll
        for (int j = 0; j < 8; j++) acc[i][j] = 0.f;

    const int ktiles = K / 16;
    for (int kt = 0; kt < ktiles; kt++) {
        // Load A tile (128 rows x 16 k) transposed into As[k][m]
#pragma unroll
        for (int i = 0; i < 2; i++) {
            int li = tid + i * 256;          // 512 float4 total
            int am = li >> 2;                // 0..127
            int ac = (li & 3) * 4;           // k offset 0,4,8,12
            float4 av = *(const float4*)(A + (size_t)(m0 + am) * K + kt * 16 + ac);
            As[ac + 0][am] = av.x;
            As[ac + 1][am] = av.y;
            As[ac + 2][am] = av.z;
            As[ac + 3][am] = av.w;

            int bk = li >> 5;                // 0..15
            int bc = (li & 31) * 4;          // 0..124
            float4 bv = *(const float4*)(B + (size_t)(kt * 16 + bk) * N + n0 + bc);
            *(float4*)&Bs[bk][bc] = bv;
        }
        __syncthreads();

#pragma unroll
        for (int k = 0; k < 16; k++) {
            float a[8], b[8];
            *(float4*)&a[0] = *(float4*)&As[k][tm];
            *(float4*)&a[4] = *(float4*)&As[k][tm + 4];
            *(float4*)&b[0] = *(float4*)&Bs[k][tn];
            *(float4*)&b[4] = *(float4*)&Bs[k][tn + 4];
#pragma unroll
            for (int i = 0; i < 8; i++)
#pragma unroll
                for (int j = 0; j < 8; j++)
                    acc[i][j] = fmaf(a[i], b[j], acc[i][j]);
        }
        __syncthreads();
    }

#pragma unroll
    for (int i = 0; i < 8; i++) {
        float* crow = C + (size_t)(m0 + tm + i) * N + n0 + tn;
        *(float4*)&crow[0] = *(float4*)&acc[i][0];
        *(float4*)&crow[4] = *(float4*)&acc[i][4];
    }
}

// ---------------------------------------------------------------------------
// RoPE: applied in-place to q and k halves of g_qkv.
// One thread per (token, head, j<64).
// ---------------------------------------------------------------------------
__global__ __launch_bounds__(256) void rope_kernel(float* __restrict__ qkv,
                                                   const int* __restrict__ positions) {
    int idx = blockIdx.x * blockDim.x + threadIdx.x;
    const int total = BB * SS * NH * HALF;
    if (idx >= total) return;
    int j = idx & 63;
    int h = (idx >> 6) & 31;
    int t = idx >> 11;                      // b*S + s
    int pos = positions[t];

    float inv_freq = powf(10000.0f, -(float)j / (float)HALF);
    float ang = (float)pos * inv_freq;
    float sn, cs;
    sincosf(ang, &sn, &cs);

    size_t base = (size_t)t * THID + h * HD;
    // q
    {
        float x1 = qkv[base + j], x2 = qkv[base + HALF + j];
        qkv[base + j]        = x1 * cs - x2 * sn;
        qkv[base + HALF + j] = x2 * cs + x1 * sn;
    }
    // k
    {
        size_t kb = base + HID;
        float x1 = qkv[kb + j], x2 = qkv[kb + HALF + j];
        qkv[kb + j]        = x1 * cs - x2 * sn;
        qkv[kb + HALF + j] = x2 * cs + x1 * sn;
    }
}

// ---------------------------------------------------------------------------
// Flash attention (causal). One block per (q_tile=64 rows, head, batch).
// 256 threads. Online softmax; O accumulator in registers (8 rows x 4 cols/thr).
// Smem strides padded (129/65) to avoid LDS bank conflicts.
// ---------------------------------------------------------------------------
#define KST 129
#define SST 65
#define FLASH_SMEM ((64*128 + 64*KST + 64*KST + 64*SST + 192) * 4)

__global__ __launch_bounds__(256) void flash_kernel(const float* __restrict__ qkv,
                                                    float* __restrict__ attn) {
    const int qt = blockIdx.x;   // 0..31
    const int h  = blockIdx.y;
    const int b  = blockIdx.z;

    extern __shared__ float sm[];
    float* Qs   = sm;                    // [64][128]
    float* Ks   = Qs + 64 * 128;         // [64][KST]
    float* Vs   = Ks + 64 * KST;         // [64][KST]
    float* Ss   = Vs + 64 * KST;         // [64][SST]
    float* m_sh = Ss + 64 * SST;         // [64]
    float* l_sh = m_sh + 64;             // [64]
    float* fac  = l_sh + 64;             // [64]

    const int tid = threadIdx.x;
    const int tr = tid >> 5;             // 0..7 : owns rows tr*8..+7 of O
    const int tc = tid & 31;             // owns cols tc+32*j
    const int r0 = (tid >> 4) * 4;       // score tile 4x4 per thread
    const int c0 = (tid & 15) * 4;

    // Load Q tile (pre-scaled)
#pragma unroll
    for (int i = 0; i < 32; i++) {
        int e = tid + i * 256;
        int r = e >> 7, c = e & 127;
        Qs[e] = qkv[(size_t)(b * SS + qt * 64 + r) * THID + h * HD + c] * SCALING;
    }
    if (tid < 64) { m_sh[tid] = -1e30f; l_sh[tid] = 0.f; }

    float o[8][4];
#pragma unroll
    for (int i = 0; i < 8; i++)
#pragma unroll
        for (int j = 0; j < 4; j++) o[i][j] = 0.f;

    __syncthreads();

    for (int j = 0; j <= qt; j++) {
        // Load K, V tiles
#pragma unroll
        for (int i = 0; i < 32; i++) {
            int e = tid + i * 256;
            int r = e >> 7, c = e & 127;
            size_t base = (size_t)(b * SS + j * 64 + r) * THID + h * HD + c;
            Ks[r * KST + c] = qkv[base + HID];
            Vs[r * KST + c] = qkv[base + 2 * HID];
        }
        __syncthreads();

        // Scores: 4x4 per thread
        float sacc[4][4];
#pragma unroll
        for (int i = 0; i < 4; i++)
#pragma unroll
            for (int jj = 0; jj < 4; jj++) sacc[i][jj] = 0.f;

        for (int d = 0; d < 128; d++) {
            float q[4], kk[4];
#pragma unroll
            for (int i = 0; i < 4; i++)  q[i]  = Qs[(r0 + i) * 128 + d];
#pragma unroll
            for (int jj = 0; jj < 4; jj++) kk[jj] = Ks[(c0 + jj) * KST + d];
#pragma unroll
            for (int i = 0; i < 4; i++)
#pragma unroll
                for (int jj = 0; jj < 4; jj++)
                    sacc[i][jj] = fmaf(q[i], kk[jj], sacc[i][jj]);
        }
        // Store with causal mask
#pragma unroll
        for (int i = 0; i < 4; i++) {
            int qg = qt * 64 + r0 + i;
#pragma unroll
            for (int jj = 0; jj < 4; jj++) {
                int kg = j * 64 + c0 + jj;
                Ss[(r0 + i) * SST + c0 + jj] = (kg <= qg) ? sacc[i][jj] : -1e30f;
            }
        }
        __syncthreads();

        // Row max + rescale factor
        if (tid < 64) {
            float mx = -1e30f;
            for (int c = 0; c < 64; c++) mx = fmaxf(mx, Ss[tid * SST + c]);
            float mnew = fmaxf(m_sh[tid], mx);
            fac[tid] = expf(m_sh[tid] - mnew);
            m_sh[tid] = mnew;
        }
        __syncthreads();

        // Exponentiate in place; rescale O registers
#pragma unroll
        for (int i = 0; i < 4; i++) {
            float mr = m_sh[r0 + i];
#pragma unroll
            for (int jj = 0; jj < 4; jj++) {
                int idx = (r0 + i) * SST + c0 + jj;
                Ss[idx] = expf(Ss[idx] - mr);
            }
        }
#pragma unroll
        for (int i = 0; i < 8; i++) {
            float f = fac[tr * 8 + i];
#pragma unroll
            for (int jj = 0; jj < 4; jj++) o[i][jj] *= f;
        }
        __syncthreads();

        // Row sums
        if (tid < 64) {
            float s = 0.f;
            for (int c = 0; c < 64; c++) s += Ss[tid * SST + c];
            l_sh[tid] = l_sh[tid] * fac[tid] + s;
        }

        // O += P @ V  (8 rows x 4 cols per thread, cols tc+32*jj : conflict-free)
        for (int c = 0; c < 64; c++) {
            float v[4];
#pragma unroll
            for (int jj = 0; jj < 4; jj++) v[jj] = Vs[c * KST + tc + 32 * jj];
#pragma unroll
            for (int i = 0; i < 8; i++) {
                float p = Ss[(tr * 8 + i) * SST + c];
#pragma unroll
                for (int jj = 0; jj < 4; jj++) o[i][jj] = fmaf(p, v[jj], o[i][jj]);
            }
        }
        __syncthreads();
    }

    // Final: normalize and write to g_attn [b, s, h*128 + d]
#pragma unroll
    for (int i = 0; i < 8; i++) {
        int r = tr * 8 + i;
        float inv = 1.f / l_sh[r];
        size_t ob = (size_t)(b * SS + qt * 64 + r) * HID + h * HD;
#pragma unroll
        for (int jj = 0; jj < 4; jj++)
            attn[ob + tc + 32 * jj] = o[i][jj] * inv;
    }
}

// ---------------------------------------------------------------------------
extern "C" void kernel_launch(void* const* d_in, const int* in_sizes, int n_in,
                              void* d_out, int out_size) {
    const int*   positions = (const int*)  d_in[0];
    const float* hidden    = (const float*)d_in[1];
    const float* Wqkv      = (const float*)d_in[2];
    const float* Wo        = (const float*)d_in[3];
    float* out = (float*)d_out;

    float *qkv, *attn;
    cudaGetSymbolAddress((void**)&qkv,  g_qkv);
    cudaGetSymbolAddress((void**)&attn, g_attn);

    // 1) QKV projection: [4096,4096] @ [4096,12288]
    gemm128<<<dim3(THID / 128, (BB * SS) / 128), 256>>>(hidden, Wqkv, qkv,
                                                        BB * SS, THID, HID);
    // 2) RoPE on q and k
    {
        int total = BB * SS * NH * HALF;
        rope_kernel<<<(total + 255) / 256, 256>>>(qkv, positions);
    }
    // 3) Causal flash attention
    cudaFuncSetAttribute(flash_kernel, cudaFuncAttributeMaxDynamicSharedMemorySize,
                         FLASH_SMEM);
    flash_kernel<<<dim3(SS / 64, NH, BB), 256, FLASH_SMEM>>>(qkv, attn);

    // 4) Output projection: [4096,4096] @ [4096,4096]
    gemm128<<<dim3(HID / 128, (BB * SS) / 128), 256>>>(attn, Wo, out,
                                                       BB * SS, HID, HID);
}

// round 3
// speedup vs baseline: 1.2378x; 1.2378x over previous
#include <cuda_runtime.h>
#include <cuda_bf16.h>
#include <math.h>
#include <stdint.h>

#define HID   4096
#define NH    32
#define HD    128
#define HALF  64
#define BB    2
#define SS    2048
#define THID  12288
#define MTOK  (BB*SS)          // 4096 tokens
#define SCALING 0.08838834764831845f   // 128^-0.5

// ---------------- scratch (__device__ globals; alloc-free) ------------------
__device__ float g_qkv [(size_t)MTOK * THID];        // [M, 3*HID]
__device__ float g_attn[(size_t)MTOK * HID];         // [M, HID]
__device__ __nv_bfloat16 g_hid_hi [(size_t)MTOK * HID];
__device__ __nv_bfloat16 g_hid_lo [(size_t)MTOK * HID];
__device__ __nv_bfloat16 g_attn_hi[(size_t)MTOK * HID];
__device__ __nv_bfloat16 g_attn_lo[(size_t)MTOK * HID];
__device__ __nv_bfloat16 g_wqkv_hi[(size_t)THID * HID];   // transposed [N][K]
__device__ __nv_bfloat16 g_wqkv_lo[(size_t)THID * HID];
__device__ __nv_bfloat16 g_wo_hi  [(size_t)HID * HID];    // transposed [N][K]
__device__ __nv_bfloat16 g_wo_lo  [(size_t)HID * HID];

// ---------------------------- asm helpers -----------------------------------
__device__ __forceinline__ uint32_t smem_u32(const void* p) {
    uint32_t a;
    asm("{ .reg .u64 t; cvta.to.shared.u64 t, %1; cvt.u32.u64 %0, t; }" : "=r"(a) : "l"(p));
    return a;
}
#define CP16(dst, src)  asm volatile("cp.async.cg.shared.global [%0], [%1], 16;" :: "r"(dst), "l"(src) : "memory")
#define CP_COMMIT()     asm volatile("cp.async.commit_group;" ::: "memory")
#define CP_WAIT2()      asm volatile("cp.async.wait_group 2;" ::: "memory")

#define LDSM4(r0,r1,r2,r3,addr)                                                \
    asm volatile("ldmatrix.sync.aligned.m8n8.x4.shared.b16 {%0,%1,%2,%3}, [%4];" \
        : "=r"(r0),"=r"(r1),"=r"(r2),"=r"(r3) : "r"(addr))

#define MMA16816(c,a,b0,b1)                                                    \
    asm volatile("mma.sync.aligned.m16n8k16.row.col.f32.bf16.bf16.f32 "        \
        "{%0,%1,%2,%3},{%4,%5,%6,%7},{%8,%9},{%0,%1,%2,%3};"                   \
        : "+f"((c)[0]),"+f"((c)[1]),"+f"((c)[2]),"+f"((c)[3])                  \
        : "r"((a)[0]),"r"((a)[1]),"r"((a)[2]),"r"((a)[3]),"r"(b0),"r"(b1))

// ---------------------------------------------------------------------------
// Convert fp32 -> (hi, lo) bf16, elementwise.
// ---------------------------------------------------------------------------
__global__ __launch_bounds__(256) void convert_hilo(const float* __restrict__ in,
                                                    __nv_bfloat16* __restrict__ hi,
                                                    __nv_bfloat16* __restrict__ lo,
                                                    size_t n4) {
    size_t i = (size_t)blockIdx.x * blockDim.x + threadIdx.x;
    if (i >= n4) return;
    float4 v = ((const float4*)in)[i];
    __nv_bfloat16 h[4], l[4];
    float x[4] = {v.x, v.y, v.z, v.w};
#pragma unroll
    for (int j = 0; j < 4; j++) {
        h[j] = __float2bfloat16(x[j]);
        l[j] = __float2bfloat16(x[j] - __bfloat162float(h[j]));
    }
    ((uint2*)hi)[i] = *(uint2*)h;
    ((uint2*)lo)[i] = *(uint2*)l;
}

// ---------------------------------------------------------------------------
// Transpose + convert: B[K][N] fp32 -> Bt hi/lo [N][K] bf16.  32x32 tiles.
// ---------------------------------------------------------------------------
__global__ __launch_bounds__(256) void transpose_hilo(const float* __restrict__ B,
                                                      __nv_bfloat16* __restrict__ th,
                                                      __nv_bfloat16* __restrict__ tl,
                                                      int K, int N) {
    __shared__ float tile[32][33];
    int n0 = blockIdx.x * 32, k0 = blockIdx.y * 32;
    int tx = threadIdx.x & 31, ty = threadIdx.x >> 5;  // 32 x 8
#pragma unroll
    for (int j = 0; j < 32; j += 8)
        tile[ty + j][tx] = B[(size_t)(k0 + ty + j) * N + n0 + tx];
    __syncthreads();
#pragma unroll
    for (int j = 0; j < 32; j += 8) {
        float x = tile[tx][ty + j];
        __nv_bfloat16 h = __float2bfloat16(x);
        __nv_bfloat16 l = __float2bfloat16(x - __bfloat162float(h));
        size_t o = (size_t)(n0 + ty + j) * K + k0 + tx;
        th[o] = h; tl[o] = l;
    }
}

// ---------------------------------------------------------------------------
// mma.sync bf16x3 GEMM: C[M,N] = A[M,K] @ Bt[N,K]^T, fp32 out.
// 128x128 CTA tile, BK=32, 4 stages, 8 warps (2m x 4n), 64x32 warp tile.
// Smem rows padded to 40 elements (80B stride: conflict-free ldmatrix).
// ---------------------------------------------------------------------------
#define SROW  40
#define BUFB  (128 * SROW * 2)      // bytes per operand buffer = 10240
#define STGB  (4 * BUFB)            // bytes per stage = 40960
#define NSTG  4
#define GEMM_DYN (NSTG * STGB + 256)

__device__ __forceinline__ void stage_copies(int tid, int m0, int n0, int kc, int K,
                                             uint32_t sbase,
                                             const __nv_bfloat16* Ah, const __nv_bfloat16* Al,
                                             const __nv_bfloat16* Bh, const __nv_bfloat16* Bl) {
#pragma unroll
    for (int i = 0; i < 8; i++) {
        int id  = tid + i * 256;       // 0..2047
        int buf = id >> 9;             // 0..3
        int idx = id & 511;
        int row = idx >> 2;            // 0..127
        int q   = idx & 3;             // 16B chunk
        uint32_t dst = sbase + buf * BUFB + row * (SROW * 2) + q * 16;
        const __nv_bfloat16* src;
        if (buf == 0)      src = Ah + (size_t)(m0 + row) * K + kc + q * 8;
        else if (buf == 1) src = Al + (size_t)(m0 + row) * K + kc + q * 8;
        else if (buf == 2) src = Bh + (size_t)(n0 + row) * K + kc + q * 8;
        else               src = Bl + (size_t)(n0 + row) * K + kc + q * 8;
        CP16(dst, src);
    }
}

__global__ __launch_bounds__(256) void gemm_mma_bf16x3(
        const __nv_bfloat16* __restrict__ Ah, const __nv_bfloat16* __restrict__ Al,
        const __nv_bfloat16* __restrict__ Bh, const __nv_bfloat16* __restrict__ Bl,
        float* __restrict__ C, int M, int N, int K) {
    extern __shared__ char dsm[];
    const uint32_t sb = (smem_u32(dsm) + 127) & ~127u;
    const int tid  = threadIdx.x;
    const int lane = tid & 31;
    const int wid  = tid >> 5;
    const int m0 = blockIdx.y * 128, n0 = blockIdx.x * 128;
    const int wm = (wid >> 2) * 64;       // warp m offset (0/64)
    const int wn = (wid & 3) * 32;        // warp n offset (0..96)

    // ldmatrix per-thread row/col (see frag layout notes)
    const int a_r = lane & 15;
    const int a_k = (lane >> 4) * 8;
    const int b_r = (lane & 7) + ((lane >> 4) << 3);
    const int b_k = ((lane >> 3) & 1) * 8;

    float acc[4][4][4];
#pragma unroll
    for (int i = 0; i < 4; i++)
#pragma unroll
        for (int j = 0; j < 4; j++)
#pragma unroll
            for (int r = 0; r < 4; r++) acc[i][j][r] = 0.f;

    const int NC = K / 32;

    // prologue: stages 0..2
#pragma unroll
    for (int s = 0; s < 3; s++) {
        stage_copies(tid, m0, n0, s * 32, K, sb + s * STGB, Ah, Al, Bh, Bl);
        CP_COMMIT();
    }

    for (int c = 0; c < NC; c++) {
        CP_WAIT2();
        __syncthreads();
        if (c + 3 < NC)
            stage_copies(tid, m0, n0, (c + 3) * 32, K, sb + ((c + 3) % NSTG) * STGB,
                         Ah, Al, Bh, Bl);
        CP_COMMIT();

        const uint32_t st = sb + (c % NSTG) * STGB;
#pragma unroll
        for (int kk = 0; kk < 32; kk += 16) {
            uint32_t ah[4][4], al[4][4], bh[4][2], bl[4][2];
#pragma unroll
            for (int mf = 0; mf < 4; mf++) {
                uint32_t ad = st + ((wm + mf * 16 + a_r) * SROW + kk + a_k) * 2;
                LDSM4(ah[mf][0], ah[mf][1], ah[mf][2], ah[mf][3], ad);
                LDSM4(al[mf][0], al[mf][1], al[mf][2], al[mf][3], ad + BUFB);
            }
#pragma unroll
            for (int ng = 0; ng < 2; ng++) {
                uint32_t bd = st + 2 * BUFB + ((wn + ng * 16 + b_r) * SROW + kk + b_k) * 2;
                uint32_t t0, t1, t2, t3;
                LDSM4(t0, t1, t2, t3, bd);
                bh[2 * ng][0] = t0; bh[2 * ng][1] = t1;
                bh[2 * ng + 1][0] = t2; bh[2 * ng + 1][1] = t3;
                LDSM4(t0, t1, t2, t3, bd + BUFB);
                bl[2 * ng][0] = t0; bl[2 * ng][1] = t1;
                bl[2 * ng + 1][0] = t2; bl[2 * ng + 1][1] = t3;
            }
#pragma unroll
            for (int mf = 0; mf < 4; mf++)
#pragma unroll
                for (int nf = 0; nf < 4; nf++)
                    MMA16816(acc[mf][nf], ah[mf], bh[nf][0], bh[nf][1]);
#pragma unroll
            for (int mf = 0; mf < 4; mf++)
#pragma unroll
                for (int nf = 0; nf < 4; nf++)
                    MMA16816(acc[mf][nf], ah[mf], bl[nf][0], bl[nf][1]);
#pragma unroll
            for (int mf = 0; mf < 4; mf++)
#pragma unroll
                for (int nf = 0; nf < 4; nf++)
                    MMA16816(acc[mf][nf], al[mf], bh[nf][0], bh[nf][1]);
        }
    }

    // write C: frag (mf,nf): rows wm+mf*16 + lane/4 (+8), cols wn+nf*8 + (lane%3)*2
    const int fr = lane >> 2;
    const int fc = (lane & 3) * 2;
#pragma unroll
    for (int mf = 0; mf < 4; mf++) {
#pragma unroll
        for (int nf = 0; nf < 4; nf++) {
            float* p0 = C + (size_t)(m0 + wm + mf * 16 + fr) * N + n0 + wn + nf * 8 + fc;
            float* p1 = p0 + 8 * N;
            p0[0] = acc[mf][nf][0]; p0[1] = acc[mf][nf][1];
            p1[0] = acc[mf][nf][2]; p1[1] = acc[mf][nf][3];
        }
    }
}

// ---------------------------------------------------------------------------
// RoPE
// ---------------------------------------------------------------------------
__global__ __launch_bounds__(256) void rope_kernel(float* __restrict__ qkv,
                                                   const int* __restrict__ positions) {
    int idx = blockIdx.x * blockDim.x + threadIdx.x;
    const int total = BB * SS * NH * HALF;
    if (idx >= total) return;
    int j = idx & 63;
    int h = (idx >> 6) & 31;
    int t = idx >> 11;
    int pos = positions[t];

    float inv_freq = powf(10000.0f, -(float)j / (float)HALF);
    float ang = (float)pos * inv_freq;
    float sn, cs;
    sincosf(ang, &sn, &cs);

    size_t base = (size_t)t * THID + h * HD;
    {
        float x1 = qkv[base + j], x2 = qkv[base + HALF + j];
        qkv[base + j]        = x1 * cs - x2 * sn;
        qkv[base + HALF + j] = x2 * cs + x1 * sn;
    }
    {
        size_t kb = base + HID;
        float x1 = qkv[kb + j], x2 = qkv[kb + HALF + j];
        qkv[kb + j]        = x1 * cs - x2 * sn;
        qkv[kb + HALF + j] = x2 * cs + x1 * sn;
    }
}

// ---------------------------------------------------------------------------
// Flash attention (unchanged; passing since R1)
// ---------------------------------------------------------------------------
#define KST 129
#define SST 65
#define FLASH_SMEM ((64*128 + 64*KST + 64*KST + 64*SST + 192) * 4)

__global__ __launch_bounds__(256) void flash_kernel(const float* __restrict__ qkv,
                                                    float* __restrict__ attn) {
    const int qt = blockIdx.x;
    const int h  = blockIdx.y;
    const int b  = blockIdx.z;

    extern __shared__ float sm[];
    float* Qs   = sm;
    float* Ks   = Qs + 64 * 128;
    float* Vs   = Ks + 64 * KST;
    float* Ss   = Vs + 64 * KST;
    float* m_sh = Ss + 64 * SST;
    float* l_sh = m_sh + 64;
    float* fac  = l_sh + 64;

    const int tid = threadIdx.x;
    const int tr = tid >> 5;
    const int tc = tid & 31;
    const int r0 = (tid >> 4) * 4;
    const int c0 = (tid & 15) * 4;

#pragma unroll
    for (int i = 0; i < 32; i++) {
        int e = tid + i * 256;
        int r = e >> 7, c = e & 127;
        Qs[e] = qkv[(size_t)(b * SS + qt * 64 + r) * THID + h * HD + c] * SCALING;
    }
    if (tid < 64) { m_sh[tid] = -1e30f; l_sh[tid] = 0.f; }

    float o[8][4];
#pragma unroll
    for (int i = 0; i < 8; i++)
#pragma unroll
        for (int j = 0; j < 4; j++) o[i][j] = 0.f;

    __syncthreads();

    for (int j = 0; j <= qt; j++) {
#pragma unroll
        for (int i = 0; i < 32; i++) {
            int e = tid + i * 256;
            int r = e >> 7, c = e & 127;
            size_t base = (size_t)(b * SS + j * 64 + r) * THID + h * HD + c;
            Ks[r * KST + c] = qkv[base + HID];
            Vs[r * KST + c] = qkv[base + 2 * HID];
        }
        __syncthreads();

        float sacc[4][4];
#pragma unroll
        for (int i = 0; i < 4; i++)
#pragma unroll
            for (int jj = 0; jj < 4; jj++) sacc[i][jj] = 0.f;

        for (int d = 0; d < 128; d++) {
            float q[4], kk[4];
#pragma unroll
            for (int i = 0; i < 4; i++)  q[i]  = Qs[(r0 + i) * 128 + d];
#pragma unroll
            for (int jj = 0; jj < 4; jj++) kk[jj] = Ks[(c0 + jj) * KST + d];
#pragma unroll
            for (int i = 0; i < 4; i++)
#pragma unroll
                for (int jj = 0; jj < 4; jj++)
                    sacc[i][jj] = fmaf(q[i], kk[jj], sacc[i][jj]);
        }
#pragma unroll
        for (int i = 0; i < 4; i++) {
            int qg = qt * 64 + r0 + i;
#pragma unroll
            for (int jj = 0; jj < 4; jj++) {
                int kg = j * 64 + c0 + jj;
                Ss[(r0 + i) * SST + c0 + jj] = (kg <= qg) ? sacc[i][jj] : -1e30f;
            }
        }
        __syncthreads();

        if (tid < 64) {
            float mx = -1e30f;
            for (int c = 0; c < 64; c++) mx = fmaxf(mx, Ss[tid * SST + c]);
            float mnew = fmaxf(m_sh[tid], mx);
            fac[tid] = expf(m_sh[tid] - mnew);
            m_sh[tid] = mnew;
        }
        __syncthreads();

#pragma unroll
        for (int i = 0; i < 4; i++) {
            float mr = m_sh[r0 + i];
#pragma unroll
            for (int jj = 0; jj < 4; jj++) {
                int idx = (r0 + i) * SST + c0 + jj;
                Ss[idx] = expf(Ss[idx] - mr);
            }
        }
#pragma unroll
        for (int i = 0; i < 8; i++) {
            float f = fac[tr * 8 + i];
#pragma unroll
            for (int jj = 0; jj < 4; jj++) o[i][jj] *= f;
        }
        __syncthreads();

        if (tid < 64) {
            float s = 0.f;
            for (int c = 0; c < 64; c++) s += Ss[tid * SST + c];
            l_sh[tid] = l_sh[tid] * fac[tid] + s;
        }

        for (int c = 0; c < 64; c++) {
            float v[4];
#pragma unroll
            for (int jj = 0; jj < 4; jj++) v[jj] = Vs[c * KST + tc + 32 * jj];
#pragma unroll
            for (int i = 0; i < 8; i++) {
                float p = Ss[(tr * 8 + i) * SST + c];
#pragma unroll
                for (int jj = 0; jj < 4; jj++) o[i][jj] = fmaf(p, v[jj], o[i][jj]);
            }
        }
        __syncthreads();
    }

#pragma unroll
    for (int i = 0; i < 8; i++) {
        int r = tr * 8 + i;
        float inv = 1.f / l_sh[r];
        size_t ob = (size_t)(b * SS + qt * 64 + r) * HID + h * HD;
#pragma unroll
        for (int jj = 0; jj < 4; jj++)
            attn[ob + tc + 32 * jj] = o[i][jj] * inv;
    }
}

// ---------------------------------------------------------------------------
extern "C" void kernel_launch(void* const* d_in, const int* in_sizes, int n_in,
                              void* d_out, int out_size) {
    const int*   positions = (const int*)  d_in[0];
    const float* hidden    = (const float*)d_in[1];
    const float* Wqkv      = (const float*)d_in[2];
    const float* Wo        = (const float*)d_in[3];
    float* out = (float*)d_out;

    float *qkv, *attn;
    __nv_bfloat16 *hh, *hl, *ah, *al, *qh, *ql, *oh, *ol;
    cudaGetSymbolAddress((void**)&qkv,  g_qkv);
    cudaGetSymbolAddress((void**)&attn, g_attn);
    cudaGetSymbolAddress((void**)&hh, g_hid_hi);
    cudaGetSymbolAddress((void**)&hl, g_hid_lo);
    cudaGetSymbolAddress((void**)&ah, g_attn_hi);
    cudaGetSymbolAddress((void**)&al, g_attn_lo);
    cudaGetSymbolAddress((void**)&qh, g_wqkv_hi);
    cudaGetSymbolAddress((void**)&ql, g_wqkv_lo);
    cudaGetSymbolAddress((void**)&oh, g_wo_hi);
    cudaGetSymbolAddress((void**)&ol, g_wo_lo);

    cudaFuncSetAttribute(gemm_mma_bf16x3, cudaFuncAttributeMaxDynamicSharedMemorySize, GEMM_DYN);
    cudaFuncSetAttribute(flash_kernel, cudaFuncAttributeMaxDynamicSharedMemorySize, FLASH_SMEM);

    // 1) hidden -> hi/lo
    {
        size_t n4 = (size_t)MTOK * HID / 4;
        convert_hilo<<<(unsigned)((n4 + 255) / 256), 256>>>(hidden, hh, hl, n4);
    }
    // 2) Wqkv -> transposed hi/lo  [12288][4096]
    transpose_hilo<<<dim3(THID / 32, HID / 32), 256>>>(Wqkv, qh, ql, HID, THID);
    // 3) QKV projection
    gemm_mma_bf16x3<<<dim3(THID / 128, MTOK / 128), 256, GEMM_DYN>>>(hh, hl, qh, ql, qkv,
                                                                     MTOK, THID, HID);
    // 4) RoPE
    {
        int total = BB * SS * NH * HALF;
        rope_kernel<<<(total + 255) / 256, 256>>>(qkv, positions);
    }
    // 5) Flash attention
    flash_kernel<<<dim3(SS / 64, NH, BB), 256, FLASH_SMEM>>>(qkv, attn);
    // 6) attn -> hi/lo
    {
        size_t n4 = (size_t)MTOK * HID / 4;
        convert_hilo<<<(unsigned)((n4 + 255) / 256), 256>>>(attn, ah, al, n4);
    }
    // 7) Wo -> transposed hi/lo
    transpose_hilo<<<dim3(HID / 32, HID / 32), 256>>>(Wo, oh, ol, HID, HID);
    // 8) Output projection
    gemm_mma_bf16x3<<<dim3(HID / 128, MTOK / 128), 256, GEMM_DYN>>>(ah, al, oh, ol, out,
                                                                    MTOK, HID, HID);
}

// round 4
// speedup vs baseline: 2.3166x; 1.8715x over previous
#include <cuda_runtime.h>
#include <cuda_bf16.h>
#include <math.h>
#include <stdint.h>

#define HID   4096
#define NH    32
#define HD    128
#define HALF  64
#define BB    2
#define SS    2048
#define THID  12288
#define MTOK  (BB*SS)
#define SCALING 0.08838834764831845f

// ---------------- scratch ----------------------------------------------------
__device__ float g_qkv [(size_t)MTOK * THID];
__device__ float g_attn[(size_t)MTOK * HID];
__device__ __nv_bfloat16 g_hid_hi [(size_t)MTOK * HID];
__device__ __nv_bfloat16 g_hid_lo [(size_t)MTOK * HID];
__device__ __nv_bfloat16 g_attn_hi[(size_t)MTOK * HID];
__device__ __nv_bfloat16 g_attn_lo[(size_t)MTOK * HID];
__device__ __nv_bfloat16 g_wqkv_hi[(size_t)THID * HID];   // [N][K]
__device__ __nv_bfloat16 g_wqkv_lo[(size_t)THID * HID];
__device__ __nv_bfloat16 g_wo_hi  [(size_t)HID * HID];
__device__ __nv_bfloat16 g_wo_lo  [(size_t)HID * HID];

// ---------------------------- asm helpers -----------------------------------
__device__ __forceinline__ uint32_t smem_u32(const void* p) {
    uint32_t a;
    asm("{ .reg .u64 t; cvta.to.shared.u64 t, %1; cvt.u32.u64 %0, t; }" : "=r"(a) : "l"(p));
    return a;
}
#define CP16(dst, src)  asm volatile("cp.async.cg.shared.global [%0], [%1], 16;" :: "r"(dst), "l"(src) : "memory")
#define CP_COMMIT()     asm volatile("cp.async.commit_group;" ::: "memory")
#define CP_WAIT1()      asm volatile("cp.async.wait_group 1;" ::: "memory")

#define LDSM4(r0,r1,r2,r3,addr)                                                \
    asm volatile("ldmatrix.sync.aligned.m8n8.x4.shared.b16 {%0,%1,%2,%3}, [%4];" \
        : "=r"(r0),"=r"(r1),"=r"(r2),"=r"(r3) : "r"(addr))

#define MMA16816(c,a,b0,b1)                                                    \
    asm volatile("mma.sync.aligned.m16n8k16.row.col.f32.bf16.bf16.f32 "        \
        "{%0,%1,%2,%3},{%4,%5,%6,%7},{%8,%9},{%0,%1,%2,%3};"                   \
        : "+f"((c)[0]),"+f"((c)[1]),"+f"((c)[2]),"+f"((c)[3])                  \
        : "r"((a)[0]),"r"((a)[1]),"r"((a)[2]),"r"((a)[3]),"r"(b0),"r"(b1))

// swizzled byte offset inside one 128x32 bf16 buffer (64B rows, 16B granules)
__device__ __forceinline__ uint32_t swz(int row, int g) {
    return (uint32_t)(row * 64 + ((g ^ ((row >> 1) & 3)) << 4));
}

// ---------------------------------------------------------------------------
// fp32 -> (hi, lo) bf16
// ---------------------------------------------------------------------------
__global__ __launch_bounds__(256) void convert_hilo(const float* __restrict__ in,
                                                    __nv_bfloat16* __restrict__ hi,
                                                    __nv_bfloat16* __restrict__ lo,
                                                    size_t n4) {
    size_t i = (size_t)blockIdx.x * blockDim.x + threadIdx.x;
    if (i >= n4) return;
    float4 v = ((const float4*)in)[i];
    __nv_bfloat16 h[4], l[4];
    float x[4] = {v.x, v.y, v.z, v.w};
#pragma unroll
    for (int j = 0; j < 4; j++) {
        h[j] = __float2bfloat16(x[j]);
        l[j] = __float2bfloat16(x[j] - __bfloat162float(h[j]));
    }
    ((uint2*)hi)[i] = *(uint2*)h;
    ((uint2*)lo)[i] = *(uint2*)l;
}

// ---------------------------------------------------------------------------
// Transpose + convert: B[K][N] fp32 -> Bt hi/lo [N][K]
// ---------------------------------------------------------------------------
__global__ __launch_bounds__(256) void transpose_hilo(const float* __restrict__ B,
                                                      __nv_bfloat16* __restrict__ th,
                                                      __nv_bfloat16* __restrict__ tl,
                                                      int K, int N) {
    __shared__ float tile[32][33];
    int n0 = blockIdx.x * 32, k0 = blockIdx.y * 32;
    int tx = threadIdx.x & 31, ty = threadIdx.x >> 5;
#pragma unroll
    for (int j = 0; j < 32; j += 8)
        tile[ty + j][tx] = B[(size_t)(k0 + ty + j) * N + n0 + tx];
    __syncthreads();
#pragma unroll
    for (int j = 0; j < 32; j += 8) {
        float x = tile[tx][ty + j];
        __nv_bfloat16 h = __float2bfloat16(x);
        __nv_bfloat16 l = __float2bfloat16(x - __bfloat162float(h));
        size_t o = (size_t)(n0 + ty + j) * K + k0 + tx;
        th[o] = h; tl[o] = l;
    }
}

// ---------------------------------------------------------------------------
// bf16x3 GEMM on mma.sync. 128x128 CTA tile, BK=32, 3 stages (32KB each),
// XOR-swizzled smem, 2 CTAs/SM.
// ---------------------------------------------------------------------------
#define BUFB  8192                 // 128 rows x 64B
#define STGB  (4 * BUFB)           // Ah, Al, Bh, Bl
#define NSTG  3
#define GEMM_DYN (NSTG * STGB)

__device__ __forceinline__ void stage_copies(int tid, int m0, int n0, int kc, int K,
                                             uint32_t sbase,
                                             const __nv_bfloat16* Ah, const __nv_bfloat16* Al,
                                             const __nv_bfloat16* Bh, const __nv_bfloat16* Bl) {
#pragma unroll
    for (int i = 0; i < 8; i++) {
        int id  = tid + i * 256;       // 0..2047
        int buf = id >> 9;
        int idx = id & 511;
        int row = idx >> 2;            // 0..127
        int g   = idx & 3;
        uint32_t dst = sbase + buf * BUFB + swz(row, g);
        const __nv_bfloat16* src;
        if (buf == 0)      src = Ah + (size_t)(m0 + row) * K + kc + g * 8;
        else if (buf == 1) src = Al + (size_t)(m0 + row) * K + kc + g * 8;
        else if (buf == 2) src = Bh + (size_t)(n0 + row) * K + kc + g * 8;
        else               src = Bl + (size_t)(n0 + row) * K + kc + g * 8;
        CP16(dst, src);
    }
    CP_COMMIT();
}

__global__ __launch_bounds__(256, 2) void gemm_mma_bf16x3(
        const __nv_bfloat16* __restrict__ Ah, const __nv_bfloat16* __restrict__ Al,
        const __nv_bfloat16* __restrict__ Bh, const __nv_bfloat16* __restrict__ Bl,
        float* __restrict__ C, int M, int N, int K) {
    extern __shared__ char dsm[];
    const uint32_t sb = smem_u32(dsm);
    const int tid  = threadIdx.x;
    const int lane = tid & 31;
    const int wid  = tid >> 5;
    const int m0 = blockIdx.y * 128, n0 = blockIdx.x * 128;
    const int wm = (wid >> 2) * 64;
    const int wn = (wid & 3) * 32;

    const int a_r = lane & 15;
    const int a_g0 = lane >> 4;            // 0/1 : k-granule offset within 16-k
    const int b_r = (lane & 7) + ((lane >> 4) << 3);
    const int b_g0 = (lane >> 3) & 1;

    float acc[4][4][4];
#pragma unroll
    for (int i = 0; i < 4; i++)
#pragma unroll
        for (int j = 0; j < 4; j++)
#pragma unroll
            for (int r = 0; r < 4; r++) acc[i][j][r] = 0.f;

    const int NC = K / 32;

    stage_copies(tid, m0, n0, 0,  K, sb,        Ah, Al, Bh, Bl);
    stage_copies(tid, m0, n0, 32, K, sb + STGB, Ah, Al, Bh, Bl);

    uint32_t st = sb;
    for (int c = 0; c < NC; c++) {
        CP_WAIT1();
        __syncthreads();
        if (c + 2 < NC)
            stage_copies(tid, m0, n0, (c + 2) * 32, K,
                         sb + ((c + 2) % NSTG) * STGB, Ah, Al, Bh, Bl);
        else
            CP_COMMIT();   // keep group count in lockstep

#pragma unroll
        for (int kk = 0; kk < 2; kk++) {           // two 16-k steps
            const int gbase = kk * 2;              // granule base (16 k = 2 granules)
            uint32_t ah[4][4], al[4][4], bh[4][2], bl[4][2];
#pragma unroll
            for (int mf = 0; mf < 4; mf++) {
                int R = wm + mf * 16 + a_r;
                uint32_t ad = st + swz(R, gbase + a_g0);
                LDSM4(ah[mf][0], ah[mf][1], ah[mf][2], ah[mf][3], ad);
                LDSM4(al[mf][0], al[mf][1], al[mf][2], al[mf][3], ad + BUFB);
            }
#pragma unroll
            for (int ng = 0; ng < 2; ng++) {
                int R = wn + ng * 16 + b_r;
                uint32_t bd = st + 2 * BUFB + swz(R, gbase + b_g0);
                uint32_t t0, t1, t2, t3;
                LDSM4(t0, t1, t2, t3, bd);
                bh[2 * ng][0] = t0; bh[2 * ng][1] = t1;
                bh[2 * ng + 1][0] = t2; bh[2 * ng + 1][1] = t3;
                LDSM4(t0, t1, t2, t3, bd + BUFB);
                bl[2 * ng][0] = t0; bl[2 * ng][1] = t1;
                bl[2 * ng + 1][0] = t2; bl[2 * ng + 1][1] = t3;
            }
#pragma unroll
            for (int mf = 0; mf < 4; mf++)
#pragma unroll
                for (int nf = 0; nf < 4; nf++)
                    MMA16816(acc[mf][nf], ah[mf], bh[nf][0], bh[nf][1]);
#pragma unroll
            for (int mf = 0; mf < 4; mf++)
#pragma unroll
                for (int nf = 0; nf < 4; nf++)
                    MMA16816(acc[mf][nf], ah[mf], bl[nf][0], bl[nf][1]);
#pragma unroll
            for (int mf = 0; mf < 4; mf++)
#pragma unroll
                for (int nf = 0; nf < 4; nf++)
                    MMA16816(acc[mf][nf], al[mf], bh[nf][0], bh[nf][1]);
        }
        st += STGB;
        if (st == sb + NSTG * STGB) st = sb;
    }

    const int fr = lane >> 2;
    const int fc = (lane & 3) * 2;
#pragma unroll
    for (int mf = 0; mf < 4; mf++) {
#pragma unroll
        for (int nf = 0; nf < 4; nf++) {
            float* p0 = C + (size_t)(m0 + wm + mf * 16 + fr) * N + n0 + wn + nf * 8 + fc;
            float* p1 = p0 + 8 * N;
            p0[0] = acc[mf][nf][0]; p0[1] = acc[mf][nf][1];
            p1[0] = acc[mf][nf][2]; p1[1] = acc[mf][nf][3];
        }
    }
}

// ---------------------------------------------------------------------------
// RoPE
// ---------------------------------------------------------------------------
__global__ __launch_bounds__(256) void rope_kernel(float* __restrict__ qkv,
                                                   const int* __restrict__ positions) {
    int idx = blockIdx.x * blockDim.x + threadIdx.x;
    const int total = BB * SS * NH * HALF;
    if (idx >= total) return;
    int j = idx & 63;
    int h = (idx >> 6) & 31;
    int t = idx >> 11;
    int pos = positions[t];

    float inv_freq = powf(10000.0f, -(float)j / (float)HALF);
    float ang = (float)pos * inv_freq;
    float sn, cs;
    sincosf(ang, &sn, &cs);

    size_t base = (size_t)t * THID + h * HD;
    {
        float x1 = qkv[base + j], x2 = qkv[base + HALF + j];
        qkv[base + j]        = x1 * cs - x2 * sn;
        qkv[base + HALF + j] = x2 * cs + x1 * sn;
    }
    {
        size_t kb = base + HID;
        float x1 = qkv[kb + j], x2 = qkv[kb + HALF + j];
        qkv[kb + j]        = x1 * cs - x2 * sn;
        qkv[kb + HALF + j] = x2 * cs + x1 * sn;
    }
}

// ---------------------------------------------------------------------------
// Flash attention
// ---------------------------------------------------------------------------
#define KST 129
#define SST 65
#define FLASH_SMEM ((64*128 + 64*KST + 64*KST + 64*SST + 192) * 4)

__global__ __launch_bounds__(256) void flash_kernel(const float* __restrict__ qkv,
                                                    float* __restrict__ attn) {
    const int qt = blockIdx.x;
    const int h  = blockIdx.y;
    const int b  = blockIdx.z;

    extern __shared__ float sm[];
    float* Qs   = sm;
    float* Ks   = Qs + 64 * 128;
    float* Vs   = Ks + 64 * KST;
    float* Ss   = Vs + 64 * KST;
    float* m_sh = Ss + 64 * SST;
    float* l_sh = m_sh + 64;
    float* fac  = l_sh + 64;

    const int tid = threadIdx.x;
    const int tr = tid >> 5;
    const int tc = tid & 31;
    const int r0 = (tid >> 4) * 4;
    const int c0 = (tid & 15) * 4;

#pragma unroll
    for (int i = 0; i < 32; i++) {
        int e = tid + i * 256;
        int r = e >> 7, c = e & 127;
        Qs[e] = qkv[(size_t)(b * SS + qt * 64 + r) * THID + h * HD + c] * SCALING;
    }
    if (tid < 64) { m_sh[tid] = -1e30f; l_sh[tid] = 0.f; }

    float o[8][4];
#pragma unroll
    for (int i = 0; i < 8; i++)
#pragma unroll
        for (int j = 0; j < 4; j++) o[i][j] = 0.f;

    __syncthreads();

    for (int j = 0; j <= qt; j++) {
#pragma unroll
        for (int i = 0; i < 32; i++) {
            int e = tid + i * 256;
            int r = e >> 7, c = e & 127;
            size_t base = (size_t)(b * SS + j * 64 + r) * THID + h * HD + c;
            Ks[r * KST + c] = qkv[base + HID];
            Vs[r * KST + c] = qkv[base + 2 * HID];
        }
        __syncthreads();

        float sacc[4][4];
#pragma unroll
        for (int i = 0; i < 4; i++)
#pragma unroll
            for (int jj = 0; jj < 4; jj++) sacc[i][jj] = 0.f;

        for (int d = 0; d < 128; d++) {
            float q[4], kk[4];
#pragma unroll
            for (int i = 0; i < 4; i++)  q[i]  = Qs[(r0 + i) * 128 + d];
#pragma unroll
            for (int jj = 0; jj < 4; jj++) kk[jj] = Ks[(c0 + jj) * KST + d];
#pragma unroll
            for (int i = 0; i < 4; i++)
#pragma unroll
                for (int jj = 0; jj < 4; jj++)
                    sacc[i][jj] = fmaf(q[i], kk[jj], sacc[i][jj]);
        }
#pragma unroll
        for (int i = 0; i < 4; i++) {
            int qg = qt * 64 + r0 + i;
#pragma unroll
            for (int jj = 0; jj < 4; jj++) {
                int kg = j * 64 + c0 + jj;
                Ss[(r0 + i) * SST + c0 + jj] = (kg <= qg) ? sacc[i][jj] : -1e30f;
            }
        }
        __syncthreads();

        if (tid < 64) {
            float mx = -1e30f;
            for (int c = 0; c < 64; c++) mx = fmaxf(mx, Ss[tid * SST + c]);
            float mnew = fmaxf(m_sh[tid], mx);
            fac[tid] = __expf(m_sh[tid] - mnew);
            m_sh[tid] = mnew;
        }
        __syncthreads();

#pragma unroll
        for (int i = 0; i < 4; i++) {
            float mr = m_sh[r0 + i];
#pragma unroll
            for (int jj = 0; jj < 4; jj++) {
                int idx = (r0 + i) * SST + c0 + jj;
                Ss[idx] = __expf(Ss[idx] - mr);
            }
        }
#pragma unroll
        for (int i = 0; i < 8; i++) {
            float f = fac[tr * 8 + i];
#pragma unroll
            for (int jj = 0; jj < 4; jj++) o[i][jj] *= f;
        }
        __syncthreads();

        if (tid < 64) {
            float s = 0.f;
            for (int c = 0; c < 64; c++) s += Ss[tid * SST + c];
            l_sh[tid] = l_sh[tid] * fac[tid] + s;
        }

        for (int c = 0; c < 64; c++) {
            float v[4];
#pragma unroll
            for (int jj = 0; jj < 4; jj++) v[jj] = Vs[c * KST + tc + 32 * jj];
#pragma unroll
            for (int i = 0; i < 8; i++) {
                float p = Ss[(tr * 8 + i) * SST + c];
#pragma unroll
                for (int jj = 0; jj < 4; jj++) o[i][jj] = fmaf(p, v[jj], o[i][jj]);
            }
        }
        __syncthreads();
    }

#pragma unroll
    for (int i = 0; i < 8; i++) {
        int r = tr * 8 + i;
        float inv = 1.f / l_sh[r];
        size_t ob = (size_t)(b * SS + qt * 64 + r) * HID + h * HD;
#pragma unroll
        for (int jj = 0; jj < 4; jj++)
            attn[ob + tc + 32 * jj] = o[i][jj] * inv;
    }
}

// ---------------------------------------------------------------------------
extern "C" void kernel_launch(void* const* d_in, const int* in_sizes, int n_in,
                              void* d_out, int out_size) {
    const int*   positions = (const int*)  d_in[0];
    const float* hidden    = (const float*)d_in[1];
    const float* Wqkv      = (const float*)d_in[2];
    const float* Wo        = (const float*)d_in[3];
    float* out = (float*)d_out;

    float *qkv, *attn;
    __nv_bfloat16 *hh, *hl, *ah, *al, *qh, *ql, *oh, *ol;
    cudaGetSymbolAddress((void**)&qkv,  g_qkv);
    cudaGetSymbolAddress((void**)&attn, g_attn);
    cudaGetSymbolAddress((void**)&hh, g_hid_hi);
    cudaGetSymbolAddress((void**)&hl, g_hid_lo);
    cudaGetSymbolAddress((void**)&ah, g_attn_hi);
    cudaGetSymbolAddress((void**)&al, g_attn_lo);
    cudaGetSymbolAddress((void**)&qh, g_wqkv_hi);
    cudaGetSymbolAddress((void**)&ql, g_wqkv_lo);
    cudaGetSymbolAddress((void**)&oh, g_wo_hi);
    cudaGetSymbolAddress((void**)&ol, g_wo_lo);

    cudaFuncSetAttribute(gemm_mma_bf16x3, cudaFuncAttributeMaxDynamicSharedMemorySize, GEMM_DYN);
    cudaFuncSetAttribute(flash_kernel, cudaFuncAttributeMaxDynamicSharedMemorySize, FLASH_SMEM);

    {
        size_t n4 = (size_t)MTOK * HID / 4;
        convert_hilo<<<(unsigned)((n4 + 255) / 256), 256>>>(hidden, hh, hl, n4);
    }
    transpose_hilo<<<dim3(THID / 32, HID / 32), 256>>>(Wqkv, qh, ql, HID, THID);
    gemm_mma_bf16x3<<<dim3(THID / 128, MTOK / 128), 256, GEMM_DYN>>>(hh, hl, qh, ql, qkv,
                                                                     MTOK, THID, HID);
    {
        int total = BB * SS * NH * HALF;
        rope_kernel<<<(total + 255) / 256, 256>>>(qkv, positions);
    }
    flash_kernel<<<dim3(SS / 64, NH, BB), 256, FLASH_SMEM>>>(qkv, attn);
    {
        size_t n4 = (size_t)MTOK * HID / 4;
        convert_hilo<<<(unsigned)((n4 + 255) / 256), 256>>>(attn, ah, al, n4);
    }
    transpose_hilo<<<dim3(HID / 32, HID / 32), 256>>>(Wo, oh, ol, HID, HID);
    gemm_mma_bf16x3<<<dim3(HID / 128, MTOK / 128), 256, GEMM_DYN>>>(ah, al, oh, ol, out,
                                                                    MTOK, HID, HID);
}

// round 5
// speedup vs baseline: 2.3911x; 1.0322x over previous
#include <cuda_runtime.h>
#include <cuda_bf16.h>
#include <math.h>
#include <stdint.h>

#define HID   4096
#define NH    32
#define HD    128
#define HALF  64
#define BB    2
#define SS    2048
#define THID  12288
#define MTOK  (BB*SS)
#define SCALING 0.08838834764831845f

// ---------------- scratch ----------------------------------------------------
__device__ float g_qkv [(size_t)MTOK * THID];
__device__ __nv_bfloat16 g_hid_hi [(size_t)MTOK * HID];
__device__ __nv_bfloat16 g_hid_lo [(size_t)MTOK * HID];
__device__ __nv_bfloat16 g_attn_hi[(size_t)MTOK * HID];
__device__ __nv_bfloat16 g_attn_lo[(size_t)MTOK * HID];
__device__ __nv_bfloat16 g_wqkv_hi[(size_t)THID * HID];   // [N][K]
__device__ __nv_bfloat16 g_wqkv_lo[(size_t)THID * HID];
__device__ __nv_bfloat16 g_wo_hi  [(size_t)HID * HID];
__device__ __nv_bfloat16 g_wo_lo  [(size_t)HID * HID];

// ---------------------------- asm helpers -----------------------------------
__device__ __forceinline__ uint32_t smem_u32(const void* p) {
    uint32_t a;
    asm("{ .reg .u64 t; cvta.to.shared.u64 t, %1; cvt.u32.u64 %0, t; }" : "=r"(a) : "l"(p));
    return a;
}
#define CP16(dst, src)  asm volatile("cp.async.cg.shared.global [%0], [%1], 16;" :: "r"(dst), "l"(src) : "memory")
#define CP_COMMIT()     asm volatile("cp.async.commit_group;" ::: "memory")
#define CP_WAIT1()      asm volatile("cp.async.wait_group 1;" ::: "memory")

#define LDSM4(r0,r1,r2,r3,addr)                                                \
    asm volatile("ldmatrix.sync.aligned.m8n8.x4.shared.b16 {%0,%1,%2,%3}, [%4];" \
        : "=r"(r0),"=r"(r1),"=r"(r2),"=r"(r3) : "r"(addr))

#define MMA16816(c,a,b0,b1)                                                    \
    asm volatile("mma.sync.aligned.m16n8k16.row.col.f32.bf16.bf16.f32 "        \
        "{%0,%1,%2,%3},{%4,%5,%6,%7},{%8,%9},{%0,%1,%2,%3};"                   \
        : "+f"((c)[0]),"+f"((c)[1]),"+f"((c)[2]),"+f"((c)[3])                  \
        : "r"((a)[0]),"r"((a)[1]),"r"((a)[2]),"r"((a)[3]),"r"(b0),"r"(b1))

// swizzled byte offset inside one 128x32 bf16 buffer (64B rows, 16B granules)
__device__ __forceinline__ uint32_t swz(int row, int g) {
    return (uint32_t)(row * 64 + ((g ^ ((row >> 1) & 3)) << 4));
}

// ---------------------------------------------------------------------------
// fp32 -> (hi, lo) bf16
// ---------------------------------------------------------------------------
__global__ __launch_bounds__(256) void convert_hilo(const float* __restrict__ in,
                                                    __nv_bfloat16* __restrict__ hi,
                                                    __nv_bfloat16* __restrict__ lo,
                                                    size_t n4) {
    size_t i = (size_t)blockIdx.x * blockDim.x + threadIdx.x;
    if (i >= n4) return;
    float4 v = ((const float4*)in)[i];
    __nv_bfloat16 h[4], l[4];
    float x[4] = {v.x, v.y, v.z, v.w};
#pragma unroll
    for (int j = 0; j < 4; j++) {
        h[j] = __float2bfloat16(x[j]);
        l[j] = __float2bfloat16(x[j] - __bfloat162float(h[j]));
    }
    ((uint2*)hi)[i] = *(uint2*)h;
    ((uint2*)lo)[i] = *(uint2*)l;
}

// ---------------------------------------------------------------------------
// Transpose + convert: B[K][N] fp32 -> Bt hi/lo [N][K]
// ---------------------------------------------------------------------------
__global__ __launch_bounds__(256) void transpose_hilo(const float* __restrict__ B,
                                                      __nv_bfloat16* __restrict__ th,
                                                      __nv_bfloat16* __restrict__ tl,
                                                      int K, int N) {
    __shared__ float tile[32][33];
    int n0 = blockIdx.x * 32, k0 = blockIdx.y * 32;
    int tx = threadIdx.x & 31, ty = threadIdx.x >> 5;
#pragma unroll
    for (int j = 0; j < 32; j += 8)
        tile[ty + j][tx] = B[(size_t)(k0 + ty + j) * N + n0 + tx];
    __syncthreads();
#pragma unroll
    for (int j = 0; j < 32; j += 8) {
        float x = tile[tx][ty + j];
        __nv_bfloat16 h = __float2bfloat16(x);
        __nv_bfloat16 l = __float2bfloat16(x - __bfloat162float(h));
        size_t o = (size_t)(n0 + ty + j) * K + k0 + tx;
        th[o] = h; tl[o] = l;
    }
}

// ---------------------------------------------------------------------------
// bf16x3 GEMM on mma.sync. 128x128 CTA tile, BK=32, 3 stages (32KB each),
// XOR-swizzled smem, 2 CTAs/SM. Pass order staged to minimize live registers.
// ---------------------------------------------------------------------------
#define BUFB  8192                 // 128 rows x 64B
#define STGB  (4 * BUFB)           // Ah, Al, Bh, Bl
#define NSTG  3
#define GEMM_DYN (NSTG * STGB)

__device__ __forceinline__ void stage_copies(int tid, int m0, int n0, int kc, int K,
                                             uint32_t sbase,
                                             const __nv_bfloat16* Ah, const __nv_bfloat16* Al,
                                             const __nv_bfloat16* Bh, const __nv_bfloat16* Bl) {
#pragma unroll
    for (int i = 0; i < 8; i++) {
        int id  = tid + i * 256;       // 0..2047
        int buf = id >> 9;
        int idx = id & 511;
        int row = idx >> 2;            // 0..127
        int g   = idx & 3;
        uint32_t dst = sbase + buf * BUFB + swz(row, g);
        const __nv_bfloat16* src;
        if (buf == 0)      src = Ah + (size_t)(m0 + row) * K + kc + g * 8;
        else if (buf == 1) src = Al + (size_t)(m0 + row) * K + kc + g * 8;
        else if (buf == 2) src = Bh + (size_t)(n0 + row) * K + kc + g * 8;
        else               src = Bl + (size_t)(n0 + row) * K + kc + g * 8;
        CP16(dst, src);
    }
    CP_COMMIT();
}

__global__ __launch_bounds__(256, 2) void gemm_mma_bf16x3(
        const __nv_bfloat16* __restrict__ Ah, const __nv_bfloat16* __restrict__ Al,
        const __nv_bfloat16* __restrict__ Bh, const __nv_bfloat16* __restrict__ Bl,
        float* __restrict__ C, int M, int N, int K) {
    extern __shared__ char dsm[];
    const uint32_t sb = smem_u32(dsm);
    const int tid  = threadIdx.x;
    const int lane = tid & 31;
    const int wid  = tid >> 5;
    const int m0 = blockIdx.y * 128, n0 = blockIdx.x * 128;
    const int wm = (wid >> 2) * 64;
    const int wn = (wid & 3) * 32;

    const int a_r  = lane & 15;
    const int a_g0 = lane >> 4;
    const int b_r  = (lane & 7) + ((lane >> 4) << 3);
    const int b_g0 = (lane >> 3) & 1;

    float acc[4][4][4];
#pragma unroll
    for (int i = 0; i < 4; i++)
#pragma unroll
        for (int j = 0; j < 4; j++)
#pragma unroll
            for (int r = 0; r < 4; r++) acc[i][j][r] = 0.f;

    const int NC = K / 32;

    stage_copies(tid, m0, n0, 0,  K, sb,        Ah, Al, Bh, Bl);
    stage_copies(tid, m0, n0, 32, K, sb + STGB, Ah, Al, Bh, Bl);

    uint32_t st = sb;
    for (int c = 0; c < NC; c++) {
        CP_WAIT1();
        __syncthreads();
        if (c + 2 < NC)
            stage_copies(tid, m0, n0, (c + 2) * 32, K,
                         sb + ((c + 2) % NSTG) * STGB, Ah, Al, Bh, Bl);
        else
            CP_COMMIT();

#pragma unroll
        for (int kk = 0; kk < 2; kk++) {
            const int gbase = kk * 2;

            // --- pass 1: Ah x Bh ---
            uint32_t ah[4][4];
#pragma unroll
            for (int mf = 0; mf < 4; mf++) {
                uint32_t ad = st + swz(wm + mf * 16 + a_r, gbase + a_g0);
                LDSM4(ah[mf][0], ah[mf][1], ah[mf][2], ah[mf][3], ad);
            }
            uint32_t bh[4][2];
#pragma unroll
            for (int ng = 0; ng < 2; ng++) {
                uint32_t bd = st + 2 * BUFB + swz(wn + ng * 16 + b_r, gbase + b_g0);
                uint32_t t0, t1, t2, t3;
                LDSM4(t0, t1, t2, t3, bd);
                bh[2 * ng][0] = t0; bh[2 * ng][1] = t1;
                bh[2 * ng + 1][0] = t2; bh[2 * ng + 1][1] = t3;
            }
#pragma unroll
            for (int mf = 0; mf < 4; mf++)
#pragma unroll
                for (int nf = 0; nf < 4; nf++)
                    MMA16816(acc[mf][nf], ah[mf], bh[nf][0], bh[nf][1]);

            // --- pass 2: Ah x Bl ---
            {
                uint32_t bl[4][2];
#pragma unroll
                for (int ng = 0; ng < 2; ng++) {
                    uint32_t bd = st + 3 * BUFB + swz(wn + ng * 16 + b_r, gbase + b_g0);
                    uint32_t t0, t1, t2, t3;
                    LDSM4(t0, t1, t2, t3, bd);
                    bl[2 * ng][0] = t0; bl[2 * ng][1] = t1;
                    bl[2 * ng + 1][0] = t2; bl[2 * ng + 1][1] = t3;
                }
#pragma unroll
                for (int mf = 0; mf < 4; mf++)
#pragma unroll
                    for (int nf = 0; nf < 4; nf++)
                        MMA16816(acc[mf][nf], ah[mf], bl[nf][0], bl[nf][1]);
            }

            // --- pass 3: Al x Bh (reuse ah registers for al) ---
#pragma unroll
            for (int mf = 0; mf < 4; mf++) {
                uint32_t ad = st + BUFB + swz(wm + mf * 16 + a_r, gbase + a_g0);
                LDSM4(ah[mf][0], ah[mf][1], ah[mf][2], ah[mf][3], ad);
            }
#pragma unroll
            for (int mf = 0; mf < 4; mf++)
#pragma unroll
                for (int nf = 0; nf < 4; nf++)
                    MMA16816(acc[mf][nf], ah[mf], bh[nf][0], bh[nf][1]);
        }
        st += STGB;
        if (st == sb + NSTG * STGB) st = sb;
    }

    const int fr = lane >> 2;
    const int fc = (lane & 3) * 2;
#pragma unroll
    for (int mf = 0; mf < 4; mf++) {
#pragma unroll
        for (int nf = 0; nf < 4; nf++) {
            float* p0 = C + (size_t)(m0 + wm + mf * 16 + fr) * N + n0 + wn + nf * 8 + fc;
            float* p1 = p0 + 8 * N;
            p0[0] = acc[mf][nf][0]; p0[1] = acc[mf][nf][1];
            p1[0] = acc[mf][nf][2]; p1[1] = acc[mf][nf][3];
        }
    }
}

// ---------------------------------------------------------------------------
// RoPE
// ---------------------------------------------------------------------------
__global__ __launch_bounds__(256) void rope_kernel(float* __restrict__ qkv,
                                                   const int* __restrict__ positions) {
    int idx = blockIdx.x * blockDim.x + threadIdx.x;
    const int total = BB * SS * NH * HALF;
    if (idx >= total) return;
    int j = idx & 63;
    int h = (idx >> 6) & 31;
    int t = idx >> 11;
    int pos = positions[t];

    float inv_freq = powf(10000.0f, -(float)j / (float)HALF);
    float ang = (float)pos * inv_freq;
    float sn, cs;
    sincosf(ang, &sn, &cs);

    size_t base = (size_t)t * THID + h * HD;
    {
        float x1 = qkv[base + j], x2 = qkv[base + HALF + j];
        qkv[base + j]        = x1 * cs - x2 * sn;
        qkv[base + HALF + j] = x2 * cs + x1 * sn;
    }
    {
        size_t kb = base + HID;
        float x1 = qkv[kb + j], x2 = qkv[kb + HALF + j];
        qkv[kb + j]        = x1 * cs - x2 * sn;
        qkv[kb + HALF + j] = x2 * cs + x1 * sn;
    }
}

// ---------------------------------------------------------------------------
// Flash attention; epilogue writes bf16 hi/lo directly (fused convert).
// ---------------------------------------------------------------------------
#define KST 129
#define SST 65
#define FLASH_SMEM ((64*128 + 64*KST + 64*KST + 64*SST + 192) * 4)

__global__ __launch_bounds__(256) void flash_kernel(const float* __restrict__ qkv,
                                                    __nv_bfloat16* __restrict__ ahi,
                                                    __nv_bfloat16* __restrict__ alo) {
    const int qt = blockIdx.x;
    const int h  = blockIdx.y;
    const int b  = blockIdx.z;

    extern __shared__ float sm[];
    float* Qs   = sm;
    float* Ks   = Qs + 64 * 128;
    float* Vs   = Ks + 64 * KST;
    float* Ss   = Vs + 64 * KST;
    float* m_sh = Ss + 64 * SST;
    float* l_sh = m_sh + 64;
    float* fac  = l_sh + 64;

    const int tid = threadIdx.x;
    const int tr = tid >> 5;
    const int tc = tid & 31;
    const int r0 = (tid >> 4) * 4;
    const int c0 = (tid & 15) * 4;

#pragma unroll
    for (int i = 0; i < 32; i++) {
        int e = tid + i * 256;
        int r = e >> 7, c = e & 127;
        Qs[e] = qkv[(size_t)(b * SS + qt * 64 + r) * THID + h * HD + c] * SCALING;
    }
    if (tid < 64) { m_sh[tid] = -1e30f; l_sh[tid] = 0.f; }

    float o[8][4];
#pragma unroll
    for (int i = 0; i < 8; i++)
#pragma unroll
        for (int j = 0; j < 4; j++) o[i][j] = 0.f;

    __syncthreads();

    for (int j = 0; j <= qt; j++) {
#pragma unroll
        for (int i = 0; i < 32; i++) {
            int e = tid + i * 256;
            int r = e >> 7, c = e & 127;
            size_t base = (size_t)(b * SS + j * 64 + r) * THID + h * HD + c;
            Ks[r * KST + c] = qkv[base + HID];
            Vs[r * KST + c] = qkv[base + 2 * HID];
        }
        __syncthreads();

        float sacc[4][4];
#pragma unroll
        for (int i = 0; i < 4; i++)
#pragma unroll
            for (int jj = 0; jj < 4; jj++) sacc[i][jj] = 0.f;

        for (int d = 0; d < 128; d++) {
            float q[4], kk[4];
#pragma unroll
            for (int i = 0; i < 4; i++)  q[i]  = Qs[(r0 + i) * 128 + d];
#pragma unroll
            for (int jj = 0; jj < 4; jj++) kk[jj] = Ks[(c0 + jj) * KST + d];
#pragma unroll
            for (int i = 0; i < 4; i++)
#pragma unroll
                for (int jj = 0; jj < 4; jj++)
                    sacc[i][jj] = fmaf(q[i], kk[jj], sacc[i][jj]);
        }
#pragma unroll
        for (int i = 0; i < 4; i++) {
            int qg = qt * 64 + r0 + i;
#pragma unroll
            for (int jj = 0; jj < 4; jj++) {
                int kg = j * 64 + c0 + jj;
                Ss[(r0 + i) * SST + c0 + jj] = (kg <= qg) ? sacc[i][jj] : -1e30f;
            }
        }
        __syncthreads();

        if (tid < 64) {
            float mx = -1e30f;
            for (int c = 0; c < 64; c++) mx = fmaxf(mx, Ss[tid * SST + c]);
            float mnew = fmaxf(m_sh[tid], mx);
            fac[tid] = __expf(m_sh[tid] - mnew);
            m_sh[tid] = mnew;
        }
        __syncthreads();

#pragma unroll
        for (int i = 0; i < 4; i++) {
            float mr = m_sh[r0 + i];
#pragma unroll
            for (int jj = 0; jj < 4; jj++) {
                int idx = (r0 + i) * SST + c0 + jj;
                Ss[idx] = __expf(Ss[idx] - mr);
            }
        }
#pragma unroll
        for (int i = 0; i < 8; i++) {
            float f = fac[tr * 8 + i];
#pragma unroll
            for (int jj = 0; jj < 4; jj++) o[i][jj] *= f;
        }
        __syncthreads();

        if (tid < 64) {
            float s = 0.f;
            for (int c = 0; c < 64; c++) s += Ss[tid * SST + c];
            l_sh[tid] = l_sh[tid] * fac[tid] + s;
        }

        for (int c = 0; c < 64; c++) {
            float v[4];
#pragma unroll
            for (int jj = 0; jj < 4; jj++) v[jj] = Vs[c * KST + tc + 32 * jj];
#pragma unroll
            for (int i = 0; i < 8; i++) {
                float p = Ss[(tr * 8 + i) * SST + c];
#pragma unroll
                for (int jj = 0; jj < 4; jj++) o[i][jj] = fmaf(p, v[jj], o[i][jj]);
            }
        }
        __syncthreads();
    }

#pragma unroll
    for (int i = 0; i < 8; i++) {
        int r = tr * 8 + i;
        float inv = 1.f / l_sh[r];
        size_t ob = (size_t)(b * SS + qt * 64 + r) * HID + h * HD;
#pragma unroll
        for (int jj = 0; jj < 4; jj++) {
            float x = o[i][jj] * inv;
            __nv_bfloat16 hh = __float2bfloat16(x);
            ahi[ob + tc + 32 * jj] = hh;
            alo[ob + tc + 32 * jj] = __float2bfloat16(x - __bfloat162float(hh));
        }
    }
}

// ---------------------------------------------------------------------------
extern "C" void kernel_launch(void* const* d_in, const int* in_sizes, int n_in,
                              void* d_out, int out_size) {
    const int*   positions = (const int*)  d_in[0];
    const float* hidden    = (const float*)d_in[1];
    const float* Wqkv      = (const float*)d_in[2];
    const float* Wo        = (const float*)d_in[3];
    float* out = (float*)d_out;

    float *qkv;
    __nv_bfloat16 *hh, *hl, *ah, *al, *qh, *ql, *oh, *ol;
    cudaGetSymbolAddress((void**)&qkv,  g_qkv);
    cudaGetSymbolAddress((void**)&hh, g_hid_hi);
    cudaGetSymbolAddress((void**)&hl, g_hid_lo);
    cudaGetSymbolAddress((void**)&ah, g_attn_hi);
    cudaGetSymbolAddress((void**)&al, g_attn_lo);
    cudaGetSymbolAddress((void**)&qh, g_wqkv_hi);
    cudaGetSymbolAddress((void**)&ql, g_wqkv_lo);
    cudaGetSymbolAddress((void**)&oh, g_wo_hi);
    cudaGetSymbolAddress((void**)&ol, g_wo_lo);

    cudaFuncSetAttribute(gemm_mma_bf16x3, cudaFuncAttributeMaxDynamicSharedMemorySize, GEMM_DYN);
    cudaFuncSetAttribute(flash_kernel, cudaFuncAttributeMaxDynamicSharedMemorySize, FLASH_SMEM);

    {
        size_t n4 = (size_t)MTOK * HID / 4;
        convert_hilo<<<(unsigned)((n4 + 255) / 256), 256>>>(hidden, hh, hl, n4);
    }
    transpose_hilo<<<dim3(THID / 32, HID / 32), 256>>>(Wqkv, qh, ql, HID, THID);
    gemm_mma_bf16x3<<<dim3(THID / 128, MTOK / 128), 256, GEMM_DYN>>>(hh, hl, qh, ql, qkv,
                                                                     MTOK, THID, HID);
    {
        int total = BB * SS * NH * HALF;
        rope_kernel<<<(total + 255) / 256, 256>>>(qkv, positions);
    }
    flash_kernel<<<dim3(SS / 64, NH, BB), 256, FLASH_SMEM>>>(qkv, ah, al);
    transpose_hilo<<<dim3(HID / 32, HID / 32), 256>>>(Wo, oh, ol, HID, HID);
    gemm_mma_bf16x3<<<dim3(HID / 128, MTOK / 128), 256, GEMM_DYN>>>(ah, al, oh, ol, out,
                                                                    MTOK, HID, HID);
}

// round 6
// speedup vs baseline: 2.9203x; 1.2213x over previous
#include <cuda_runtime.h>
#include <cuda_fp16.h>
#include <math.h>
#include <stdint.h>

#define HID   4096
#define NH    32
#define HD    128
#define HALF  64
#define BB    2
#define SS    2048
#define THID  12288
#define MTOK  (BB*SS)
#define SCALING 0.08838834764831845f

// ---------------- scratch ----------------------------------------------------
__device__ float g_qkv [(size_t)MTOK * THID];
__device__ __half g_hid_h [(size_t)MTOK * HID];          // activations, single fp16
__device__ __half g_attn_h[(size_t)MTOK * HID];
__device__ __half g_wqkv_hi[(size_t)THID * HID];         // weights transposed [N][K]
__device__ __half g_wqkv_lo[(size_t)THID * HID];
__device__ __half g_wo_hi  [(size_t)HID * HID];
__device__ __half g_wo_lo  [(size_t)HID * HID];

// ---------------------------- asm helpers -----------------------------------
__device__ __forceinline__ uint32_t smem_u32(const void* p) {
    uint32_t a;
    asm("{ .reg .u64 t; cvta.to.shared.u64 t, %1; cvt.u32.u64 %0, t; }" : "=r"(a) : "l"(p));
    return a;
}
#define CP16(dst, src)  asm volatile("cp.async.cg.shared.global [%0], [%1], 16;" :: "r"(dst), "l"(src) : "memory")
#define CP_COMMIT()     asm volatile("cp.async.commit_group;" ::: "memory")
#define CP_WAIT1()      asm volatile("cp.async.wait_group 1;" ::: "memory")

#define LDSM4(r0,r1,r2,r3,addr)                                                \
    asm volatile("ldmatrix.sync.aligned.m8n8.x4.shared.b16 {%0,%1,%2,%3}, [%4];" \
        : "=r"(r0),"=r"(r1),"=r"(r2),"=r"(r3) : "r"(addr))

#define MMA16816(c,a,b0,b1)                                                    \
    asm volatile("mma.sync.aligned.m16n8k16.row.col.f32.f16.f16.f32 "          \
        "{%0,%1,%2,%3},{%4,%5,%6,%7},{%8,%9},{%0,%1,%2,%3};"                   \
        : "+f"((c)[0]),"+f"((c)[1]),"+f"((c)[2]),"+f"((c)[3])                  \
        : "r"((a)[0]),"r"((a)[1]),"r"((a)[2]),"r"((a)[3]),"r"(b0),"r"(b1))

// swizzled byte offset inside one 128x32 fp16 buffer (64B rows, 16B granules)
__device__ __forceinline__ uint32_t swz(int row, int g) {
    return (uint32_t)(row * 64 + ((g ^ ((row >> 1) & 3)) << 4));
}

// ---------------------------------------------------------------------------
// fp32 -> fp16 (single), elementwise
// ---------------------------------------------------------------------------
__global__ __launch_bounds__(256) void convert_h(const float* __restrict__ in,
                                                 __half* __restrict__ hi, size_t n4) {
    size_t i = (size_t)blockIdx.x * blockDim.x + threadIdx.x;
    if (i >= n4) return;
    float4 v = ((const float4*)in)[i];
    __half h[4] = {__float2half(v.x), __float2half(v.y),
                   __float2half(v.z), __float2half(v.w)};
    ((uint2*)hi)[i] = *(uint2*)h;
}

// ---------------------------------------------------------------------------
// Transpose + fp16 hi/lo split: B[K][N] fp32 -> Bt hi/lo [N][K]
// ---------------------------------------------------------------------------
__global__ __launch_bounds__(256) void transpose_hilo(const float* __restrict__ B,
                                                      __half* __restrict__ th,
                                                      __half* __restrict__ tl,
                                                      int K, int N) {
    __shared__ float tile[32][33];
    int n0 = blockIdx.x * 32, k0 = blockIdx.y * 32;
    int tx = threadIdx.x & 31, ty = threadIdx.x >> 5;
#pragma unroll
    for (int j = 0; j < 32; j += 8)
        tile[ty + j][tx] = B[(size_t)(k0 + ty + j) * N + n0 + tx];
    __syncthreads();
#pragma unroll
    for (int j = 0; j < 32; j += 8) {
        float x = tile[tx][ty + j];
        __half h = __float2half(x);
        __half l = __float2half(x - __half2float(h));
        size_t o = (size_t)(n0 + ty + j) * K + k0 + tx;
        th[o] = h; tl[o] = l;
    }
}

// ---------------------------------------------------------------------------
// fp16x2 GEMM on mma.sync: C = A @ Bt^T with A fp16, B split hi/lo.
// 128x128 CTA tile, BK=32, 3 stages x 24KB, 2 CTAs/SM.
// ---------------------------------------------------------------------------
#define BUFB  8192                 // 128 rows x 64B
#define STGB  (3 * BUFB)           // Ah, Bh, Bl
#define NSTG  3
#define GEMM_DYN (NSTG * STGB)

__device__ __forceinline__ void stage_copies(int tid, int m0, int n0, int kc, int K,
                                             uint32_t sbase,
                                             const __half* Ah,
                                             const __half* Bh, const __half* Bl) {
#pragma unroll
    for (int i = 0; i < 6; i++) {
        int id  = tid + i * 256;       // 0..1535
        int buf = id >> 9;             // 0..2
        int idx = id & 511;
        int row = idx >> 2;            // 0..127
        int g   = idx & 3;
        uint32_t dst = sbase + buf * BUFB + swz(row, g);
        const __half* src;
        if (buf == 0)      src = Ah + (size_t)(m0 + row) * K + kc + g * 8;
        else if (buf == 1) src = Bh + (size_t)(n0 + row) * K + kc + g * 8;
        else               src = Bl + (size_t)(n0 + row) * K + kc + g * 8;
        CP16(dst, src);
    }
    CP_COMMIT();
}

__global__ __launch_bounds__(256, 2) void gemm_mma_f16x2(
        const __half* __restrict__ Ah,
        const __half* __restrict__ Bh, const __half* __restrict__ Bl,
        float* __restrict__ C, int M, int N, int K) {
    extern __shared__ char dsm[];
    const uint32_t sb = smem_u32(dsm);
    const int tid  = threadIdx.x;
    const int lane = tid & 31;
    const int wid  = tid >> 5;
    const int m0 = blockIdx.y * 128, n0 = blockIdx.x * 128;
    const int wm = (wid >> 2) * 64;
    const int wn = (wid & 3) * 32;

    const int a_r  = lane & 15;
    const int a_g0 = lane >> 4;
    const int b_r  = (lane & 7) + ((lane >> 4) << 3);
    const int b_g0 = (lane >> 3) & 1;

    float acc[4][4][4];
#pragma unroll
    for (int i = 0; i < 4; i++)
#pragma unroll
        for (int j = 0; j < 4; j++)
#pragma unroll
            for (int r = 0; r < 4; r++) acc[i][j][r] = 0.f;

    const int NC = K / 32;

    stage_copies(tid, m0, n0, 0,  K, sb,        Ah, Bh, Bl);
    stage_copies(tid, m0, n0, 32, K, sb + STGB, Ah, Bh, Bl);

    uint32_t st = sb;
    for (int c = 0; c < NC; c++) {
        CP_WAIT1();
        __syncthreads();
        if (c + 2 < NC)
            stage_copies(tid, m0, n0, (c + 2) * 32, K,
                         sb + ((c + 2) % NSTG) * STGB, Ah, Bh, Bl);
        else
            CP_COMMIT();

#pragma unroll
        for (int kk = 0; kk < 2; kk++) {
            const int gbase = kk * 2;

            uint32_t ah[4][4];
#pragma unroll
            for (int mf = 0; mf < 4; mf++) {
                uint32_t ad = st + swz(wm + mf * 16 + a_r, gbase + a_g0);
                LDSM4(ah[mf][0], ah[mf][1], ah[mf][2], ah[mf][3], ad);
            }
            uint32_t bh[4][2];
#pragma unroll
            for (int ng = 0; ng < 2; ng++) {
                uint32_t bd = st + BUFB + swz(wn + ng * 16 + b_r, gbase + b_g0);
                uint32_t t0, t1, t2, t3;
                LDSM4(t0, t1, t2, t3, bd);
                bh[2 * ng][0] = t0; bh[2 * ng][1] = t1;
                bh[2 * ng + 1][0] = t2; bh[2 * ng + 1][1] = t3;
            }
#pragma unroll
            for (int mf = 0; mf < 4; mf++)
#pragma unroll
                for (int nf = 0; nf < 4; nf++)
                    MMA16816(acc[mf][nf], ah[mf], bh[nf][0], bh[nf][1]);

            // pass 2: Ah x Bl (reuse bh regs)
#pragma unroll
            for (int ng = 0; ng < 2; ng++) {
                uint32_t bd = st + 2 * BUFB + swz(wn + ng * 16 + b_r, gbase + b_g0);
                uint32_t t0, t1, t2, t3;
                LDSM4(t0, t1, t2, t3, bd);
                bh[2 * ng][0] = t0; bh[2 * ng][1] = t1;
                bh[2 * ng + 1][0] = t2; bh[2 * ng + 1][1] = t3;
            }
#pragma unroll
            for (int mf = 0; mf < 4; mf++)
#pragma unroll
                for (int nf = 0; nf < 4; nf++)
                    MMA16816(acc[mf][nf], ah[mf], bh[nf][0], bh[nf][1]);
        }
        st += STGB;
        if (st == sb + NSTG * STGB) st = sb;
    }

    const int fr = lane >> 2;
    const int fc = (lane & 3) * 2;
#pragma unroll
    for (int mf = 0; mf < 4; mf++) {
#pragma unroll
        for (int nf = 0; nf < 4; nf++) {
            float* p0 = C + (size_t)(m0 + wm + mf * 16 + fr) * N + n0 + wn + nf * 8 + fc;
            float* p1 = p0 + 8 * N;
            p0[0] = acc[mf][nf][0]; p0[1] = acc[mf][nf][1];
            p1[0] = acc[mf][nf][2]; p1[1] = acc[mf][nf][3];
        }
    }
}

// ---------------------------------------------------------------------------
// RoPE
// ---------------------------------------------------------------------------
__global__ __launch_bounds__(256) void rope_kernel(float* __restrict__ qkv,
                                                   const int* __restrict__ positions) {
    int idx = blockIdx.x * blockDim.x + threadIdx.x;
    const int total = BB * SS * NH * HALF;
    if (idx >= total) return;
    int j = idx & 63;
    int h = (idx >> 6) & 31;
    int t = idx >> 11;
    int pos = positions[t];

    float inv_freq = powf(10000.0f, -(float)j / (float)HALF);
    float ang = (float)pos * inv_freq;
    float sn, cs;
    sincosf(ang, &sn, &cs);

    size_t base = (size_t)t * THID + h * HD;
    {
        float x1 = qkv[base + j], x2 = qkv[base + HALF + j];
        qkv[base + j]        = x1 * cs - x2 * sn;
        qkv[base + HALF + j] = x2 * cs + x1 * sn;
    }
    {
        size_t kb = base + HID;
        float x1 = qkv[kb + j], x2 = qkv[kb + HALF + j];
        qkv[kb + j]        = x1 * cs - x2 * sn;
        qkv[kb + HALF + j] = x2 * cs + x1 * sn;
    }
}

// ---------------------------------------------------------------------------
// Flash attention; epilogue writes fp16 attn directly.
// ---------------------------------------------------------------------------
#define KST 129
#define SST 65
#define FLASH_SMEM ((64*128 + 64*KST + 64*KST + 64*SST + 192) * 4)

__global__ __launch_bounds__(256) void flash_kernel(const float* __restrict__ qkv,
                                                    __half* __restrict__ ah) {
    const int qt = blockIdx.x;
    const int h  = blockIdx.y;
    const int b  = blockIdx.z;

    extern __shared__ float sm[];
    float* Qs   = sm;
    float* Ks   = Qs + 64 * 128;
    float* Vs   = Ks + 64 * KST;
    float* Ss   = Vs + 64 * KST;
    float* m_sh = Ss + 64 * SST;
    float* l_sh = m_sh + 64;
    float* fac  = l_sh + 64;

    const int tid = threadIdx.x;
    const int tr = tid >> 5;
    const int tc = tid & 31;
    const int r0 = (tid >> 4) * 4;
    const int c0 = (tid & 15) * 4;

#pragma unroll
    for (int i = 0; i < 32; i++) {
        int e = tid + i * 256;
        int r = e >> 7, c = e & 127;
        Qs[e] = qkv[(size_t)(b * SS + qt * 64 + r) * THID + h * HD + c] * SCALING;
    }
    if (tid < 64) { m_sh[tid] = -1e30f; l_sh[tid] = 0.f; }

    float o[8][4];
#pragma unroll
    for (int i = 0; i < 8; i++)
#pragma unroll
        for (int j = 0; j < 4; j++) o[i][j] = 0.f;

    __syncthreads();

    for (int j = 0; j <= qt; j++) {
#pragma unroll
        for (int i = 0; i < 32; i++) {
            int e = tid + i * 256;
            int r = e >> 7, c = e & 127;
            size_t base = (size_t)(b * SS + j * 64 + r) * THID + h * HD + c;
            Ks[r * KST + c] = qkv[base + HID];
            Vs[r * KST + c] = qkv[base + 2 * HID];
        }
        __syncthreads();

        float sacc[4][4];
#pragma unroll
        for (int i = 0; i < 4; i++)
#pragma unroll
            for (int jj = 0; jj < 4; jj++) sacc[i][jj] = 0.f;

        for (int d = 0; d < 128; d++) {
            float q[4], kk[4];
#pragma unroll
            for (int i = 0; i < 4; i++)  q[i]  = Qs[(r0 + i) * 128 + d];
#pragma unroll
            for (int jj = 0; jj < 4; jj++) kk[jj] = Ks[(c0 + jj) * KST + d];
#pragma unroll
            for (int i = 0; i < 4; i++)
#pragma unroll
                for (int jj = 0; jj < 4; jj++)
                    sacc[i][jj] = fmaf(q[i], kk[jj], sacc[i][jj]);
        }
#pragma unroll
        for (int i = 0; i < 4; i++) {
            int qg = qt * 64 + r0 + i;
#pragma unroll
            for (int jj = 0; jj < 4; jj++) {
                int kg = j * 64 + c0 + jj;
                Ss[(r0 + i) * SST + c0 + jj] = (kg <= qg) ? sacc[i][jj] : -1e30f;
            }
        }
        __syncthreads();

        if (tid < 64) {
            float mx = -1e30f;
            for (int c = 0; c < 64; c++) mx = fmaxf(mx, Ss[tid * SST + c]);
            float mnew = fmaxf(m_sh[tid], mx);
            fac[tid] = __expf(m_sh[tid] - mnew);
            m_sh[tid] = mnew;
        }
        __syncthreads();

#pragma unroll
        for (int i = 0; i < 4; i++) {
            float mr = m_sh[r0 + i];
#pragma unroll
            for (int jj = 0; jj < 4; jj++) {
                int idx = (r0 + i) * SST + c0 + jj;
                Ss[idx] = __expf(Ss[idx] - mr);
            }
        }
#pragma unroll
        for (int i = 0; i < 8; i++) {
            float f = fac[tr * 8 + i];
#pragma unroll
            for (int jj = 0; jj < 4; jj++) o[i][jj] *= f;
        }
        __syncthreads();

        if (tid < 64) {
            float s = 0.f;
            for (int c = 0; c < 64; c++) s += Ss[tid * SST + c];
            l_sh[tid] = l_sh[tid] * fac[tid] + s;
        }

        for (int c = 0; c < 64; c++) {
            float v[4];
#pragma unroll
            for (int jj = 0; jj < 4; jj++) v[jj] = Vs[c * KST + tc + 32 * jj];
#pragma unroll
            for (int i = 0; i < 8; i++) {
                float p = Ss[(tr * 8 + i) * SST + c];
#pragma unroll
                for (int jj = 0; jj < 4; jj++) o[i][jj] = fmaf(p, v[jj], o[i][jj]);
            }
        }
        __syncthreads();
    }

#pragma unroll
    for (int i = 0; i < 8; i++) {
        int r = tr * 8 + i;
        float inv = 1.f / l_sh[r];
        size_t ob = (size_t)(b * SS + qt * 64 + r) * HID + h * HD;
#pragma unroll
        for (int jj = 0; jj < 4; jj++)
            ah[ob + tc + 32 * jj] = __float2half(o[i][jj] * inv);
    }
}

// ---------------------------------------------------------------------------
extern "C" void kernel_launch(void* const* d_in, const int* in_sizes, int n_in,
                              void* d_out, int out_size) {
    const int*   positions = (const int*)  d_in[0];
    const float* hidden    = (const float*)d_in[1];
    const float* Wqkv      = (const float*)d_in[2];
    const float* Wo        = (const float*)d_in[3];
    float* out = (float*)d_out;

    float *qkv;
    __half *hh, *ah, *qh, *ql, *oh, *ol;
    cudaGetSymbolAddress((void**)&qkv, g_qkv);
    cudaGetSymbolAddress((void**)&hh, g_hid_h);
    cudaGetSymbolAddress((void**)&ah, g_attn_h);
    cudaGetSymbolAddress((void**)&qh, g_wqkv_hi);
    cudaGetSymbolAddress((void**)&ql, g_wqkv_lo);
    cudaGetSymbolAddress((void**)&oh, g_wo_hi);
    cudaGetSymbolAddress((void**)&ol, g_wo_lo);

    cudaFuncSetAttribute(gemm_mma_f16x2, cudaFuncAttributeMaxDynamicSharedMemorySize, GEMM_DYN);
    cudaFuncSetAttribute(flash_kernel, cudaFuncAttributeMaxDynamicSharedMemorySize, FLASH_SMEM);

    {
        size_t n4 = (size_t)MTOK * HID / 4;
        convert_h<<<(unsigned)((n4 + 255) / 256), 256>>>(hidden, hh, n4);
    }
    transpose_hilo<<<dim3(THID / 32, HID / 32), 256>>>(Wqkv, qh, ql, HID, THID);
    gemm_mma_f16x2<<<dim3(THID / 128, MTOK / 128), 256, GEMM_DYN>>>(hh, qh, ql, qkv,
                                                                    MTOK, THID, HID);
    {
        int total = BB * SS * NH * HALF;
        rope_kernel<<<(total + 255) / 256, 256>>>(qkv, positions);
    }
    flash_kernel<<<dim3(SS / 64, NH, BB), 256, FLASH_SMEM>>>(qkv, ah);
    transpose_hilo<<<dim3(HID / 32, HID / 32), 256>>>(Wo, oh, ol, HID, HID);
    gemm_mma_f16x2<<<dim3(HID / 128, MTOK / 128), 256, GEMM_DYN>>>(ah, oh, ol, out,
                                                                   MTOK, HID, HID);
}

// round 7
// speedup vs baseline: 3.4884x; 1.1945x over previous
#include <cuda_runtime.h>
#include <cuda_fp16.h>
#include <math.h>
#include <stdint.h>

#define HID   4096
#define NH    32
#define HD    128
#define HALF  64
#define BB    2
#define SS    2048
#define THID  12288
#define MTOK  (BB*SS)
#define SCALING 0.08838834764831845f

// ---------------- scratch ----------------------------------------------------
__device__ float g_qkv [(size_t)MTOK * THID];
__device__ __half g_hid_h [(size_t)MTOK * HID];
__device__ __half g_attn_h[(size_t)MTOK * HID];
__device__ __half g_wqkv_h[(size_t)THID * HID];          // transposed [N][K], hi only
__device__ __half g_wo_hi [(size_t)HID * HID];
__device__ __half g_wo_lo [(size_t)HID * HID];

// ---------------------------- asm helpers -----------------------------------
__device__ __forceinline__ uint32_t smem_u32(const void* p) {
    uint32_t a;
    asm("{ .reg .u64 t; cvta.to.shared.u64 t, %1; cvt.u32.u64 %0, t; }" : "=r"(a) : "l"(p));
    return a;
}
#define CP16(dst, src)  asm volatile("cp.async.cg.shared.global [%0], [%1], 16;" :: "r"(dst), "l"(src) : "memory")
#define CP_COMMIT()     asm volatile("cp.async.commit_group;" ::: "memory")
#define CP_WAIT1()      asm volatile("cp.async.wait_group 1;" ::: "memory")

#define LDSM4(r0,r1,r2,r3,addr)                                                \
    asm volatile("ldmatrix.sync.aligned.m8n8.x4.shared.b16 {%0,%1,%2,%3}, [%4];" \
        : "=r"(r0),"=r"(r1),"=r"(r2),"=r"(r3) : "r"(addr))

#define MMA16816(c,a,b0,b1)                                                    \
    asm volatile("mma.sync.aligned.m16n8k16.row.col.f32.f16.f16.f32 "          \
        "{%0,%1,%2,%3},{%4,%5,%6,%7},{%8,%9},{%0,%1,%2,%3};"                   \
        : "+f"((c)[0]),"+f"((c)[1]),"+f"((c)[2]),"+f"((c)[3])                  \
        : "r"((a)[0]),"r"((a)[1]),"r"((a)[2]),"r"((a)[3]),"r"(b0),"r"(b1))

__device__ __forceinline__ uint32_t swz(int row, int g) {
    return (uint32_t)(row * 64 + ((g ^ ((row >> 1) & 3)) << 4));
}

// ---------------------------------------------------------------------------
__global__ __launch_bounds__(256) void convert_h(const float* __restrict__ in,
                                                 __half* __restrict__ hi, size_t n4) {
    size_t i = (size_t)blockIdx.x * blockDim.x + threadIdx.x;
    if (i >= n4) return;
    float4 v = ((const float4*)in)[i];
    __half h[4] = {__float2half(v.x), __float2half(v.y),
                   __float2half(v.z), __float2half(v.w)};
    ((uint2*)hi)[i] = *(uint2*)h;
}

// ---------------------------------------------------------------------------
// Transpose + fp16: B[K][N] fp32 -> Bt [N][K]; tl==nullptr skips the lo term.
// ---------------------------------------------------------------------------
__global__ __launch_bounds__(256) void transpose_hilo(const float* __restrict__ B,
                                                      __half* __restrict__ th,
                                                      __half* __restrict__ tl,
                                                      int K, int N) {
    __shared__ float tile[32][33];
    int n0 = blockIdx.x * 32, k0 = blockIdx.y * 32;
    int tx = threadIdx.x & 31, ty = threadIdx.x >> 5;
#pragma unroll
    for (int j = 0; j < 32; j += 8)
        tile[ty + j][tx] = B[(size_t)(k0 + ty + j) * N + n0 + tx];
    __syncthreads();
#pragma unroll
    for (int j = 0; j < 32; j += 8) {
        float x = tile[tx][ty + j];
        __half h = __float2half(x);
        size_t o = (size_t)(n0 + ty + j) * K + k0 + tx;
        th[o] = h;
        if (tl) tl[o] = __float2half(x - __half2float(h));
    }
}

// ---------------------------------------------------------------------------
// fp16 GEMM on mma.sync, PASSES = 1 (B hi only) or 2 (B hi/lo).
// 128x128 CTA tile, BK=32, multi-stage cp.async, 2 CTAs/SM.
// ---------------------------------------------------------------------------
#define BUFB  8192                 // 128 rows x 64B

template <int PASSES>
__device__ __forceinline__ void stage_copies(int tid, int m0, int n0, int kc, int K,
                                             uint32_t sbase,
                                             const __half* Ah,
                                             const __half* Bh, const __half* Bl) {
    constexpr int NB = 1 + PASSES;
#pragma unroll
    for (int i = 0; i < 2 * NB; i++) {
        int id  = tid + i * 256;
        int buf = id >> 9;
        int idx = id & 511;
        int row = idx >> 2;
        int g   = idx & 3;
        uint32_t dst = sbase + buf * BUFB + swz(row, g);
        const __half* src;
        if (buf == 0)      src = Ah + (size_t)(m0 + row) * K + kc + g * 8;
        else if (buf == 1) src = Bh + (size_t)(n0 + row) * K + kc + g * 8;
        else               src = Bl + (size_t)(n0 + row) * K + kc + g * 8;
        CP16(dst, src);
    }
    CP_COMMIT();
}

template <int PASSES, int NSTG>
__global__ __launch_bounds__(256, 2) void gemm_mma_f16(
        const __half* __restrict__ Ah,
        const __half* __restrict__ Bh, const __half* __restrict__ Bl,
        float* __restrict__ C, int M, int N, int K) {
    constexpr int STGB = (1 + PASSES) * BUFB;
    extern __shared__ char dsm[];
    const uint32_t sb = smem_u32(dsm);
    const int tid  = threadIdx.x;
    const int lane = tid & 31;
    const int wid  = tid >> 5;
    const int m0 = blockIdx.y * 128, n0 = blockIdx.x * 128;
    const int wm = (wid >> 2) * 64;
    const int wn = (wid & 3) * 32;

    const int a_r  = lane & 15;
    const int a_g0 = lane >> 4;
    const int b_r  = (lane & 7) + ((lane >> 4) << 3);
    const int b_g0 = (lane >> 3) & 1;

    float acc[4][4][4];
#pragma unroll
    for (int i = 0; i < 4; i++)
#pragma unroll
        for (int j = 0; j < 4; j++)
#pragma unroll
            for (int r = 0; r < 4; r++) acc[i][j][r] = 0.f;

    const int NC = K / 32;

    stage_copies<PASSES>(tid, m0, n0, 0,  K, sb,        Ah, Bh, Bl);
    stage_copies<PASSES>(tid, m0, n0, 32, K, sb + STGB, Ah, Bh, Bl);

    uint32_t st = sb;
    for (int c = 0; c < NC; c++) {
        CP_WAIT1();
        __syncthreads();
        if (c + 2 < NC)
            stage_copies<PASSES>(tid, m0, n0, (c + 2) * 32, K,
                                 sb + ((c + 2) % NSTG) * STGB, Ah, Bh, Bl);
        else
            CP_COMMIT();

#pragma unroll
        for (int kk = 0; kk < 2; kk++) {
            const int gbase = kk * 2;

            uint32_t ah[4][4];
#pragma unroll
            for (int mf = 0; mf < 4; mf++) {
                uint32_t ad = st + swz(wm + mf * 16 + a_r, gbase + a_g0);
                LDSM4(ah[mf][0], ah[mf][1], ah[mf][2], ah[mf][3], ad);
            }
            uint32_t bh[4][2];
#pragma unroll
            for (int ng = 0; ng < 2; ng++) {
                uint32_t bd = st + BUFB + swz(wn + ng * 16 + b_r, gbase + b_g0);
                uint32_t t0, t1, t2, t3;
                LDSM4(t0, t1, t2, t3, bd);
                bh[2 * ng][0] = t0; bh[2 * ng][1] = t1;
                bh[2 * ng + 1][0] = t2; bh[2 * ng + 1][1] = t3;
            }
#pragma unroll
            for (int mf = 0; mf < 4; mf++)
#pragma unroll
                for (int nf = 0; nf < 4; nf++)
                    MMA16816(acc[mf][nf], ah[mf], bh[nf][0], bh[nf][1]);

            if (PASSES == 2) {
#pragma unroll
                for (int ng = 0; ng < 2; ng++) {
                    uint32_t bd = st + 2 * BUFB + swz(wn + ng * 16 + b_r, gbase + b_g0);
                    uint32_t t0, t1, t2, t3;
                    LDSM4(t0, t1, t2, t3, bd);
                    bh[2 * ng][0] = t0; bh[2 * ng][1] = t1;
                    bh[2 * ng + 1][0] = t2; bh[2 * ng + 1][1] = t3;
                }
#pragma unroll
                for (int mf = 0; mf < 4; mf++)
#pragma unroll
                    for (int nf = 0; nf < 4; nf++)
                        MMA16816(acc[mf][nf], ah[mf], bh[nf][0], bh[nf][1]);
            }
        }
        st += STGB;
        if (st == sb + NSTG * STGB) st = sb;
    }

    const int fr = lane >> 2;
    const int fc = (lane & 3) * 2;
#pragma unroll
    for (int mf = 0; mf < 4; mf++) {
#pragma unroll
        for (int nf = 0; nf < 4; nf++) {
            float* p0 = C + (size_t)(m0 + wm + mf * 16 + fr) * N + n0 + wn + nf * 8 + fc;
            float* p1 = p0 + 8 * N;
            p0[0] = acc[mf][nf][0]; p0[1] = acc[mf][nf][1];
            p1[0] = acc[mf][nf][2]; p1[1] = acc[mf][nf][3];
        }
    }
}

// ---------------------------------------------------------------------------
__global__ __launch_bounds__(256) void rope_kernel(float* __restrict__ qkv,
                                                   const int* __restrict__ positions) {
    int idx = blockIdx.x * blockDim.x + threadIdx.x;
    const int total = BB * SS * NH * HALF;
    if (idx >= total) return;
    int j = idx & 63;
    int h = (idx >> 6) & 31;
    int t = idx >> 11;
    int pos = positions[t];

    float inv_freq = powf(10000.0f, -(float)j / (float)HALF);
    float ang = (float)pos * inv_freq;
    float sn, cs;
    sincosf(ang, &sn, &cs);

    size_t base = (size_t)t * THID + h * HD;
    {
        float x1 = qkv[base + j], x2 = qkv[base + HALF + j];
        qkv[base + j]        = x1 * cs - x2 * sn;
        qkv[base + HALF + j] = x2 * cs + x1 * sn;
    }
    {
        size_t kb = base + HID;
        float x1 = qkv[kb + j], x2 = qkv[kb + HALF + j];
        qkv[kb + j]        = x1 * cs - x2 * sn;
        qkv[kb + HALF + j] = x2 * cs + x1 * sn;
    }
}

// ---------------------------------------------------------------------------
#define KST 129
#define SST 65
#define FLASH_SMEM ((64*128 + 64*KST + 64*KST + 64*SST + 192) * 4)

__global__ __launch_bounds__(256) void flash_kernel(const float* __restrict__ qkv,
                                                    __half* __restrict__ ah) {
    const int qt = blockIdx.x;
    const int h  = blockIdx.y;
    const int b  = blockIdx.z;

    extern __shared__ float sm[];
    float* Qs   = sm;
    float* Ks   = Qs + 64 * 128;
    float* Vs   = Ks + 64 * KST;
    float* Ss   = Vs + 64 * KST;
    float* m_sh = Ss + 64 * SST;
    float* l_sh = m_sh + 64;
    float* fac  = l_sh + 64;

    const int tid = threadIdx.x;
    const int tr = tid >> 5;
    const int tc = tid & 31;
    const int r0 = (tid >> 4) * 4;
    const int c0 = (tid & 15) * 4;

#pragma unroll
    for (int i = 0; i < 32; i++) {
        int e = tid + i * 256;
        int r = e >> 7, c = e & 127;
        Qs[e] = qkv[(size_t)(b * SS + qt * 64 + r) * THID + h * HD + c] * SCALING;
    }
    if (tid < 64) { m_sh[tid] = -1e30f; l_sh[tid] = 0.f; }

    float o[8][4];
#pragma unroll
    for (int i = 0; i < 8; i++)
#pragma unroll
        for (int j = 0; j < 4; j++) o[i][j] = 0.f;

    __syncthreads();

    for (int j = 0; j <= qt; j++) {
#pragma unroll
        for (int i = 0; i < 32; i++) {
            int e = tid + i * 256;
            int r = e >> 7, c = e & 127;
            size_t base = (size_t)(b * SS + j * 64 + r) * THID + h * HD + c;
            Ks[r * KST + c] = qkv[base + HID];
            Vs[r * KST + c] = qkv[base + 2 * HID];
        }
        __syncthreads();

        float sacc[4][4];
#pragma unroll
        for (int i = 0; i < 4; i++)
#pragma unroll
            for (int jj = 0; jj < 4; jj++) sacc[i][jj] = 0.f;

        for (int d = 0; d < 128; d++) {
            float q[4], kk[4];
#pragma unroll
            for (int i = 0; i < 4; i++)  q[i]  = Qs[(r0 + i) * 128 + d];
#pragma unroll
            for (int jj = 0; jj < 4; jj++) kk[jj] = Ks[(c0 + jj) * KST + d];
#pragma unroll
            for (int i = 0; i < 4; i++)
#pragma unroll
                for (int jj = 0; jj < 4; jj++)
                    sacc[i][jj] = fmaf(q[i], kk[jj], sacc[i][jj]);
        }
#pragma unroll
        for (int i = 0; i < 4; i++) {
            int qg = qt * 64 + r0 + i;
#pragma unroll
            for (int jj = 0; jj < 4; jj++) {
                int kg = j * 64 + c0 + jj;
                Ss[(r0 + i) * SST + c0 + jj] = (kg <= qg) ? sacc[i][jj] : -1e30f;
            }
        }
        __syncthreads();

        if (tid < 64) {
            float mx = -1e30f;
            for (int c = 0; c < 64; c++) mx = fmaxf(mx, Ss[tid * SST + c]);
            float mnew = fmaxf(m_sh[tid], mx);
            fac[tid] = __expf(m_sh[tid] - mnew);
            m_sh[tid] = mnew;
        }
        __syncthreads();

#pragma unroll
        for (int i = 0; i < 4; i++) {
            float mr = m_sh[r0 + i];
#pragma unroll
            for (int jj = 0; jj < 4; jj++) {
                int idx = (r0 + i) * SST + c0 + jj;
                Ss[idx] = __expf(Ss[idx] - mr);
            }
        }
#pragma unroll
        for (int i = 0; i < 8; i++) {
            float f = fac[tr * 8 + i];
#pragma unroll
            for (int jj = 0; jj < 4; jj++) o[i][jj] *= f;
        }
        __syncthreads();

        if (tid < 64) {
            float s = 0.f;
            for (int c = 0; c < 64; c++) s += Ss[tid * SST + c];
            l_sh[tid] = l_sh[tid] * fac[tid] + s;
        }

        for (int c = 0; c < 64; c++) {
            float v[4];
#pragma unroll
            for (int jj = 0; jj < 4; jj++) v[jj] = Vs[c * KST + tc + 32 * jj];
#pragma unroll
            for (int i = 0; i < 8; i++) {
                float p = Ss[(tr * 8 + i) * SST + c];
#pragma unroll
                for (int jj = 0; jj < 4; jj++) o[i][jj] = fmaf(p, v[jj], o[i][jj]);
            }
        }
        __syncthreads();
    }

#pragma unroll
    for (int i = 0; i < 8; i++) {
        int r = tr * 8 + i;
        float inv = 1.f / l_sh[r];
        size_t ob = (size_t)(b * SS + qt * 64 + r) * HID + h * HD;
#pragma unroll
        for (int jj = 0; jj < 4; jj++)
            ah[ob + tc + 32 * jj] = __float2half(o[i][jj] * inv);
    }
}

// ---------------------------------------------------------------------------
extern "C" void kernel_launch(void* const* d_in, const int* in_sizes, int n_in,
                              void* d_out, int out_size) {
    const int*   positions = (const int*)  d_in[0];
    const float* hidden    = (const float*)d_in[1];
    const float* Wqkv      = (const float*)d_in[2];
    const float* Wo        = (const float*)d_in[3];
    float* out = (float*)d_out;

    float *qkv;
    __half *hh, *ah, *qh, *oh, *ol;
    cudaGetSymbolAddress((void**)&qkv, g_qkv);
    cudaGetSymbolAddress((void**)&hh, g_hid_h);
    cudaGetSymbolAddress((void**)&ah, g_attn_h);
    cudaGetSymbolAddress((void**)&qh, g_wqkv_h);
    cudaGetSymbolAddress((void**)&oh, g_wo_hi);
    cudaGetSymbolAddress((void**)&ol, g_wo_lo);

    const int DYN1 = 4 * (2 * BUFB);    // 4 stages x 16KB
    const int DYN2 = 3 * (3 * BUFB);    // 3 stages x 24KB
    cudaFuncSetAttribute(gemm_mma_f16<1, 4>,
                         cudaFuncAttributeMaxDynamicSharedMemorySize, DYN1);
    cudaFuncSetAttribute(gemm_mma_f16<2, 3>,
                         cudaFuncAttributeMaxDynamicSharedMemorySize, DYN2);
    cudaFuncSetAttribute(flash_kernel, cudaFuncAttributeMaxDynamicSharedMemorySize, FLASH_SMEM);

    {
        size_t n4 = (size_t)MTOK * HID / 4;
        convert_h<<<(unsigned)((n4 + 255) / 256), 256>>>(hidden, hh, n4);
    }
    transpose_hilo<<<dim3(THID / 32, HID / 32), 256>>>(Wqkv, qh, (__half*)nullptr, HID, THID);
    gemm_mma_f16<1, 4><<<dim3(THID / 128, MTOK / 128), 256, DYN1>>>(hh, qh, nullptr, qkv,
                                                                    MTOK, THID, HID);
    {
        int total = BB * SS * NH * HALF;
        rope_kernel<<<(total + 255) / 256, 256>>>(qkv, positions);
    }
    flash_kernel<<<dim3(SS / 64, NH, BB), 256, FLASH_SMEM>>>(qkv, ah);
    transpose_hilo<<<dim3(HID / 32, HID / 32), 256>>>(Wo, oh, ol, HID, HID);
    gemm_mma_f16<2, 3><<<dim3(HID / 128, MTOK / 128), 256, DYN2>>>(ah, oh, ol, out,
                                                                   MTOK, HID, HID);
}

// round 8
// speedup vs baseline: 7.1313x; 2.0443x over previous
#include <cuda_runtime.h>
#include <cuda_fp16.h>
#include <math.h>
#include <stdint.h>

#define HID   4096
#define NH    32
#define HD    128
#define HALF  64
#define BB    2
#define SS    2048
#define THID  12288
#define MTOK  (BB*SS)
#define SCALING 0.08838834764831845f

// ---------------- scratch ----------------------------------------------------
__device__ float  g_qkv [(size_t)MTOK * THID];
__device__ __half g_q_h [(size_t)MTOK * HID];    // rope'd q * SCALING, fp16
__device__ __half g_k_h [(size_t)MTOK * HID];    // rope'd k, fp16
__device__ __half g_v_h [(size_t)MTOK * HID];    // v, fp16
__device__ __half g_hid_h [(size_t)MTOK * HID];
__device__ __half g_attn_h[(size_t)MTOK * HID];
__device__ __half g_wqkv_h[(size_t)THID * HID];  // transposed [N][K]
__device__ __half g_wo_hi [(size_t)HID * HID];
__device__ __half g_wo_lo [(size_t)HID * HID];

// ---------------------------- asm helpers -----------------------------------
__device__ __forceinline__ uint32_t smem_u32(const void* p) {
    uint32_t a;
    asm("{ .reg .u64 t; cvta.to.shared.u64 t, %1; cvt.u32.u64 %0, t; }" : "=r"(a) : "l"(p));
    return a;
}
#define CP16(dst, src)  asm volatile("cp.async.cg.shared.global [%0], [%1], 16;" :: "r"(dst), "l"(src) : "memory")
#define CP_COMMIT()     asm volatile("cp.async.commit_group;" ::: "memory")
#define CP_WAIT0()      asm volatile("cp.async.wait_group 0;" ::: "memory")
#define CP_WAIT1()      asm volatile("cp.async.wait_group 1;" ::: "memory")

#define LDSM4(r0,r1,r2,r3,addr)                                                \
    asm volatile("ldmatrix.sync.aligned.m8n8.x4.shared.b16 {%0,%1,%2,%3}, [%4];" \
        : "=r"(r0),"=r"(r1),"=r"(r2),"=r"(r3) : "r"(addr))

#define LDSM4T(r0,r1,r2,r3,addr)                                               \
    asm volatile("ldmatrix.sync.aligned.m8n8.x4.trans.shared.b16 {%0,%1,%2,%3}, [%4];" \
        : "=r"(r0),"=r"(r1),"=r"(r2),"=r"(r3) : "r"(addr))

#define MMA16816(c,a,b0,b1)                                                    \
    asm volatile("mma.sync.aligned.m16n8k16.row.col.f32.f16.f16.f32 "          \
        "{%0,%1,%2,%3},{%4,%5,%6,%7},{%8,%9},{%0,%1,%2,%3};"                   \
        : "+f"((c)[0]),"+f"((c)[1]),"+f"((c)[2]),"+f"((c)[3])                  \
        : "r"((a)[0]),"r"((a)[1]),"r"((a)[2]),"r"((a)[3]),"r"(b0),"r"(b1))

// GEMM smem swizzle (64B rows, 4 granules)
__device__ __forceinline__ uint32_t swz(int row, int g) {
    return (uint32_t)(row * 64 + ((g ^ ((row >> 1) & 3)) << 4));
}
// Flash smem swizzle (256B rows, 16 granules; XOR low 3 bits)
__device__ __forceinline__ uint32_t vswz(int row, int g) {
    return (uint32_t)(row * 256 + ((g ^ (row & 7)) << 4));
}

// ---------------------------------------------------------------------------
__global__ __launch_bounds__(256) void convert_h(const float* __restrict__ in,
                                                 __half* __restrict__ hi, size_t n4) {
    size_t i = (size_t)blockIdx.x * blockDim.x + threadIdx.x;
    if (i >= n4) return;
    float4 v = ((const float4*)in)[i];
    __half h[4] = {__float2half(v.x), __float2half(v.y),
                   __float2half(v.z), __float2half(v.w)};
    ((uint2*)hi)[i] = *(uint2*)h;
}

// ---------------------------------------------------------------------------
// Transpose + fp16: B[K][N] fp32 -> Bt [N][K]; tl==nullptr skips lo term.
// ---------------------------------------------------------------------------
__global__ __launch_bounds__(256) void transpose_hilo(const float* __restrict__ B,
                                                      __half* __restrict__ th,
                                                      __half* __restrict__ tl,
                                                      int K, int N) {
    __shared__ float tile[32][33];
    int n0 = blockIdx.x * 32, k0 = blockIdx.y * 32;
    int tx = threadIdx.x & 31, ty = threadIdx.x >> 5;
#pragma unroll
    for (int j = 0; j < 32; j += 8)
        tile[ty + j][tx] = B[(size_t)(k0 + ty + j) * N + n0 + tx];
    __syncthreads();
#pragma unroll
    for (int j = 0; j < 32; j += 8) {
        float x = tile[tx][ty + j];
        __half h = __float2half(x);
        size_t o = (size_t)(n0 + ty + j) * K + k0 + tx;
        th[o] = h;
        if (tl) tl[o] = __float2half(x - __half2float(h));
    }
}

// ---------------------------------------------------------------------------
// fp16 GEMM on mma.sync, PASSES = 1 or 2. (unchanged from R7)
// ---------------------------------------------------------------------------
#define BUFB  8192

template <int PASSES>
__device__ __forceinline__ void stage_copies(int tid, int m0, int n0, int kc, int K,
                                             uint32_t sbase,
                                             const __half* Ah,
                                             const __half* Bh, const __half* Bl) {
    constexpr int NB = 1 + PASSES;
#pragma unroll
    for (int i = 0; i < 2 * NB; i++) {
        int id  = tid + i * 256;
        int buf = id >> 9;
        int idx = id & 511;
        int row = idx >> 2;
        int g   = idx & 3;
        uint32_t dst = sbase + buf * BUFB + swz(row, g);
        const __half* src;
        if (buf == 0)      src = Ah + (size_t)(m0 + row) * K + kc + g * 8;
        else if (buf == 1) src = Bh + (size_t)(n0 + row) * K + kc + g * 8;
        else               src = Bl + (size_t)(n0 + row) * K + kc + g * 8;
        CP16(dst, src);
    }
    CP_COMMIT();
}

template <int PASSES, int NSTG>
__global__ __launch_bounds__(256, 2) void gemm_mma_f16(
        const __half* __restrict__ Ah,
        const __half* __restrict__ Bh, const __half* __restrict__ Bl,
        float* __restrict__ C, int M, int N, int K) {
    constexpr int STGB = (1 + PASSES) * BUFB;
    extern __shared__ char dsm[];
    const uint32_t sb = smem_u32(dsm);
    const int tid  = threadIdx.x;
    const int lane = tid & 31;
    const int wid  = tid >> 5;
    const int m0 = blockIdx.y * 128, n0 = blockIdx.x * 128;
    const int wm = (wid >> 2) * 64;
    const int wn = (wid & 3) * 32;

    const int a_r  = lane & 15;
    const int a_g0 = lane >> 4;
    const int b_r  = (lane & 7) + ((lane >> 4) << 3);
    const int b_g0 = (lane >> 3) & 1;

    float acc[4][4][4];
#pragma unroll
    for (int i = 0; i < 4; i++)
#pragma unroll
        for (int j = 0; j < 4; j++)
#pragma unroll
            for (int r = 0; r < 4; r++) acc[i][j][r] = 0.f;

    const int NC = K / 32;
    stage_copies<PASSES>(tid, m0, n0, 0,  K, sb,        Ah, Bh, Bl);
    stage_copies<PASSES>(tid, m0, n0, 32, K, sb + STGB, Ah, Bh, Bl);

    uint32_t st = sb;
    for (int c = 0; c < NC; c++) {
        CP_WAIT1();
        __syncthreads();
        if (c + 2 < NC)
            stage_copies<PASSES>(tid, m0, n0, (c + 2) * 32, K,
                                 sb + ((c + 2) % NSTG) * STGB, Ah, Bh, Bl);
        else
            CP_COMMIT();

#pragma unroll
        for (int kk = 0; kk < 2; kk++) {
            const int gbase = kk * 2;
            uint32_t ah[4][4];
#pragma unroll
            for (int mf = 0; mf < 4; mf++) {
                uint32_t ad = st + swz(wm + mf * 16 + a_r, gbase + a_g0);
                LDSM4(ah[mf][0], ah[mf][1], ah[mf][2], ah[mf][3], ad);
            }
            uint32_t bh[4][2];
#pragma unroll
            for (int ng = 0; ng < 2; ng++) {
                uint32_t bd = st + BUFB + swz(wn + ng * 16 + b_r, gbase + b_g0);
                uint32_t t0, t1, t2, t3;
                LDSM4(t0, t1, t2, t3, bd);
                bh[2 * ng][0] = t0; bh[2 * ng][1] = t1;
                bh[2 * ng + 1][0] = t2; bh[2 * ng + 1][1] = t3;
            }
#pragma unroll
            for (int mf = 0; mf < 4; mf++)
#pragma unroll
                for (int nf = 0; nf < 4; nf++)
                    MMA16816(acc[mf][nf], ah[mf], bh[nf][0], bh[nf][1]);

            if (PASSES == 2) {
#pragma unroll
                for (int ng = 0; ng < 2; ng++) {
                    uint32_t bd = st + 2 * BUFB + swz(wn + ng * 16 + b_r, gbase + b_g0);
                    uint32_t t0, t1, t2, t3;
                    LDSM4(t0, t1, t2, t3, bd);
                    bh[2 * ng][0] = t0; bh[2 * ng][1] = t1;
                    bh[2 * ng + 1][0] = t2; bh[2 * ng + 1][1] = t3;
                }
#pragma unroll
                for (int mf = 0; mf < 4; mf++)
#pragma unroll
                    for (int nf = 0; nf < 4; nf++)
                        MMA16816(acc[mf][nf], ah[mf], bh[nf][0], bh[nf][1]);
            }
        }
        st += STGB;
        if (st == sb + NSTG * STGB) st = sb;
    }

    const int fr = lane >> 2;
    const int fc = (lane & 3) * 2;
#pragma unroll
    for (int mf = 0; mf < 4; mf++) {
#pragma unroll
        for (int nf = 0; nf < 4; nf++) {
            float* p0 = C + (size_t)(m0 + wm + mf * 16 + fr) * N + n0 + wn + nf * 8 + fc;
            float* p1 = p0 + 8 * N;
            p0[0] = acc[mf][nf][0]; p0[1] = acc[mf][nf][1];
            p1[0] = acc[mf][nf][2]; p1[1] = acc[mf][nf][3];
        }
    }
}

// ---------------------------------------------------------------------------
// RoPE: read fp32 qkv, write fp16 q (scaled), k, v.
// ---------------------------------------------------------------------------
__global__ __launch_bounds__(256) void rope_kernel(const float* __restrict__ qkv,
                                                   const int* __restrict__ positions,
                                                   __half* __restrict__ qh,
                                                   __half* __restrict__ kh,
                                                   __half* __restrict__ vh) {
    int idx = blockIdx.x * blockDim.x + threadIdx.x;
    const int total = BB * SS * NH * HALF;
    if (idx >= total) return;
    int j = idx & 63;
    int h = (idx >> 6) & 31;
    int t = idx >> 11;
    int pos = positions[t];

    float inv_freq = powf(10000.0f, -(float)j / (float)HALF);
    float ang = (float)pos * inv_freq;
    float sn, cs;
    sincosf(ang, &sn, &cs);

    size_t base = (size_t)t * THID + h * HD;
    size_t obase = (size_t)t * HID + h * HD;
    {
        float x1 = qkv[base + j], x2 = qkv[base + HALF + j];
        qh[obase + j]        = __float2half((x1 * cs - x2 * sn) * SCALING);
        qh[obase + HALF + j] = __float2half((x2 * cs + x1 * sn) * SCALING);
    }
    {
        size_t kb = base + HID;
        float x1 = qkv[kb + j], x2 = qkv[kb + HALF + j];
        kh[obase + j]        = __float2half(x1 * cs - x2 * sn);
        kh[obase + HALF + j] = __float2half(x2 * cs + x1 * sn);
    }
    {
        size_t vb = base + 2 * HID;
        vh[obase + j]        = __float2half(qkv[vb + j]);
        vh[obase + HALF + j] = __float2half(qkv[vb + HALF + j]);
    }
}

// ---------------------------------------------------------------------------
// Flash attention on HMMA. 128 threads (4 warps x 16 q-rows), 64-row Q tile.
// K/V 64x128 fp16 tiles in swizzled smem; P from S-accumulator repack.
// ---------------------------------------------------------------------------
#define FSM_Q 0
#define FSM_K 16384
#define FSM_V 32768
#define FLASH_DYN 49152

__global__ __launch_bounds__(128, 3) void flash_hmma(const __half* __restrict__ qh,
                                                     const __half* __restrict__ kh,
                                                     const __half* __restrict__ vh,
                                                     __half* __restrict__ ah) {
    const int qt = blockIdx.x;
    const int h  = blockIdx.y;
    const int b  = blockIdx.z;

    extern __shared__ char dsm[];
    const uint32_t sb = smem_u32(dsm);
    const int tid  = threadIdx.x;
    const int lane = tid & 31;
    const int wid  = tid >> 5;
    const int fr = lane >> 2;      // fragment row within 8
    const int qq = lane & 3;       // quad column index

    // ldmatrix addressing
    const int a_r  = lane & 15;
    const int a_gh = lane >> 4;
    const int b_r  = (lane & 7) + ((lane >> 4) << 3);
    const int b_gh = (lane >> 3) & 1;
    const int vk   = (lane & 7) + (((lane >> 3) & 1) << 3);  // trans: k row
    const int vg   = lane >> 4;                              // trans: n granule

    // load Q tile (64 rows x 128 dims fp16)
#pragma unroll
    for (int i = 0; i < 8; i++) {
        int idx = tid + i * 128;
        int row = idx >> 4, g = idx & 15;
        const __half* src = qh + ((size_t)(b * SS + qt * 64 + row) * HID + h * HD + g * 8);
        CP16(sb + FSM_Q + vswz(row, g), src);
    }
    CP_COMMIT();

    float o[16][4];
#pragma unroll
    for (int i = 0; i < 16; i++)
#pragma unroll
        for (int r = 0; r < 4; r++) o[i][r] = 0.f;
    float m0 = -1e30f, m1 = -1e30f, l0 = 0.f, l1 = 0.f;

    for (int j = 0; j <= qt; j++) {
        // load K, V tiles
#pragma unroll
        for (int i = 0; i < 8; i++) {
            int idx = tid + i * 128;
            int row = idx >> 4, g = idx & 15;
            size_t srco = (size_t)(b * SS + j * 64 + row) * HID + h * HD + g * 8;
            CP16(sb + FSM_K + vswz(row, g), kh + srco);
            CP16(sb + FSM_V + vswz(row, g), vh + srco);
        }
        CP_COMMIT();
        CP_WAIT0();
        __syncthreads();

        // S = Q @ K^T  (16 x 64 per warp)
        float s[8][4];
#pragma unroll
        for (int nf = 0; nf < 8; nf++)
#pragma unroll
            for (int r = 0; r < 4; r++) s[nf][r] = 0.f;

#pragma unroll
        for (int ks = 0; ks < 8; ks++) {
            uint32_t aq[4];
            LDSM4(aq[0], aq[1], aq[2], aq[3],
                  sb + FSM_Q + vswz(wid * 16 + a_r, ks * 2 + a_gh));
#pragma unroll
            for (int np = 0; np < 4; np++) {
                uint32_t t0, t1, t2, t3;
                LDSM4(t0, t1, t2, t3, sb + FSM_K + vswz(np * 16 + b_r, ks * 2 + b_gh));
                MMA16816(s[np * 2],     aq, t0, t1);
                MMA16816(s[np * 2 + 1], aq, t2, t3);
            }
        }

        // causal mask (diagonal tile only)
        if (j == qt) {
            int row0 = wid * 16 + fr;
            int row1 = row0 + 8;
#pragma unroll
            for (int nf = 0; nf < 8; nf++) {
                int c0 = nf * 8 + qq * 2;
                if (c0 > row0)     s[nf][0] = -1e30f;
                if (c0 + 1 > row0) s[nf][1] = -1e30f;
                if (c0 > row1)     s[nf][2] = -1e30f;
                if (c0 + 1 > row1) s[nf][3] = -1e30f;
            }
        }

        // row max (quad reduce)
        float mx0 = -1e30f, mx1 = -1e30f;
#pragma unroll
        for (int nf = 0; nf < 8; nf++) {
            mx0 = fmaxf(mx0, fmaxf(s[nf][0], s[nf][1]));
            mx1 = fmaxf(mx1, fmaxf(s[nf][2], s[nf][3]));
        }
        mx0 = fmaxf(mx0, __shfl_xor_sync(0xffffffffu, mx0, 1));
        mx0 = fmaxf(mx0, __shfl_xor_sync(0xffffffffu, mx0, 2));
        mx1 = fmaxf(mx1, __shfl_xor_sync(0xffffffffu, mx1, 1));
        mx1 = fmaxf(mx1, __shfl_xor_sync(0xffffffffu, mx1, 2));

        float mn0 = fmaxf(m0, mx0), mn1 = fmaxf(m1, mx1);
        float f0 = __expf(m0 - mn0), f1 = __expf(m1 - mn1);
        m0 = mn0; m1 = mn1;

        // exponentiate, row sums, pack P to half2
        uint32_t ph[8][2];
        float sum0 = 0.f, sum1 = 0.f;
#pragma unroll
        for (int nf = 0; nf < 8; nf++) {
            float p0 = __expf(s[nf][0] - m0);
            float p1 = __expf(s[nf][1] - m0);
            float p2 = __expf(s[nf][2] - m1);
            float p3 = __expf(s[nf][3] - m1);
            sum0 += p0 + p1; sum1 += p2 + p3;
            __half2 h01 = __floats2half2_rn(p0, p1);
            __half2 h23 = __floats2half2_rn(p2, p3);
            ph[nf][0] = *(uint32_t*)&h01;
            ph[nf][1] = *(uint32_t*)&h23;
        }
        sum0 += __shfl_xor_sync(0xffffffffu, sum0, 1);
        sum0 += __shfl_xor_sync(0xffffffffu, sum0, 2);
        sum1 += __shfl_xor_sync(0xffffffffu, sum1, 1);
        sum1 += __shfl_xor_sync(0xffffffffu, sum1, 2);
        l0 = l0 * f0 + sum0;
        l1 = l1 * f1 + sum1;

        // rescale O
#pragma unroll
        for (int i = 0; i < 16; i++) {
            o[i][0] *= f0; o[i][1] *= f0;
            o[i][2] *= f1; o[i][3] *= f1;
        }

        // O += P @ V
#pragma unroll
        for (int ks = 0; ks < 4; ks++) {
            uint32_t ap[4] = {ph[2 * ks][0], ph[2 * ks][1],
                              ph[2 * ks + 1][0], ph[2 * ks + 1][1]};
#pragma unroll
            for (int np = 0; np < 8; np++) {
                uint32_t t0, t1, t2, t3;
                LDSM4T(t0, t1, t2, t3, sb + FSM_V + vswz(ks * 16 + vk, np * 2 + vg));
                MMA16816(o[np * 2],     ap, t0, t1);
                MMA16816(o[np * 2 + 1], ap, t2, t3);
            }
        }
        __syncthreads();
    }

    // epilogue
    float inv0 = 1.f / l0, inv1 = 1.f / l1;
    int row0 = b * SS + qt * 64 + wid * 16 + fr;
#pragma unroll
    for (int np = 0; np < 16; np++) {
        int col = h * HD + np * 8 + qq * 2;
        __half2 v0 = __floats2half2_rn(o[np][0] * inv0, o[np][1] * inv0);
        __half2 v1 = __floats2half2_rn(o[np][2] * inv1, o[np][3] * inv1);
        *(__half2*)(ah + (size_t)row0 * HID + col) = v0;
        *(__half2*)(ah + (size_t)(row0 + 8) * HID + col) = v1;
    }
}

// ---------------------------------------------------------------------------
extern "C" void kernel_launch(void* const* d_in, const int* in_sizes, int n_in,
                              void* d_out, int out_size) {
    const int*   positions = (const int*)  d_in[0];
    const float* hidden    = (const float*)d_in[1];
    const float* Wqkv      = (const float*)d_in[2];
    const float* Wo        = (const float*)d_in[3];
    float* out = (float*)d_out;

    float *qkv;
    __half *hh, *ah, *qh, *oh, *ol, *qhx, *khx, *vhx;
    cudaGetSymbolAddress((void**)&qkv, g_qkv);
    cudaGetSymbolAddress((void**)&hh, g_hid_h);
    cudaGetSymbolAddress((void**)&ah, g_attn_h);
    cudaGetSymbolAddress((void**)&qh, g_wqkv_h);
    cudaGetSymbolAddress((void**)&oh, g_wo_hi);
    cudaGetSymbolAddress((void**)&ol, g_wo_lo);
    cudaGetSymbolAddress((void**)&qhx, g_q_h);
    cudaGetSymbolAddress((void**)&khx, g_k_h);
    cudaGetSymbolAddress((void**)&vhx, g_v_h);

    const int DYN1 = 4 * (2 * BUFB);
    const int DYN2 = 3 * (3 * BUFB);
    cudaFuncSetAttribute(gemm_mma_f16<1, 4>,
                         cudaFuncAttributeMaxDynamicSharedMemorySize, DYN1);
    cudaFuncSetAttribute(gemm_mma_f16<2, 3>,
                         cudaFuncAttributeMaxDynamicSharedMemorySize, DYN2);
    cudaFuncSetAttribute(flash_hmma,
                         cudaFuncAttributeMaxDynamicSharedMemorySize, FLASH_DYN);

    {
        size_t n4 = (size_t)MTOK * HID / 4;
        convert_h<<<(unsigned)((n4 + 255) / 256), 256>>>(hidden, hh, n4);
    }
    transpose_hilo<<<dim3(THID / 32, HID / 32), 256>>>(Wqkv, qh, (__half*)nullptr, HID, THID);
    gemm_mma_f16<1, 4><<<dim3(THID / 128, MTOK / 128), 256, DYN1>>>(hh, qh, nullptr, qkv,
                                                                    MTOK, THID, HID);
    {
        int total = BB * SS * NH * HALF;
        rope_kernel<<<(total + 255) / 256, 256>>>(qkv, positions, qhx, khx, vhx);
    }
    flash_hmma<<<dim3(SS / 64, NH, BB), 128, FLASH_DYN>>>(qhx, khx, vhx, ah);
    transpose_hilo<<<dim3(HID / 32, HID / 32), 256>>>(Wo, oh, ol, HID, HID);
    gemm_mma_f16<2, 3><<<dim3(HID / 128, MTOK / 128), 256, DYN2>>>(ah, oh, ol, out,
                                                                   MTOK, HID, HID);
}

// round 9
// speedup vs baseline: 8.2555x; 1.1577x over previous
#include <cuda_runtime.h>
#include <cuda_fp16.h>
#include <math.h>
#include <stdint.h>

#define HID   4096
#define NH    32
#define HD    128
#define HALF  64
#define BB    2
#define SS    2048
#define THID  12288
#define MTOK  (BB*SS)
#define SCALING 0.08838834764831845f

// ---------------- scratch ----------------------------------------------------
__device__ float  g_qkv [(size_t)MTOK * THID];
__device__ __half g_q_h [(size_t)MTOK * HID];
__device__ __half g_k_h [(size_t)MTOK * HID];
__device__ __half g_v_h [(size_t)MTOK * HID];
__device__ __half g_hid_h [(size_t)MTOK * HID];
__device__ __half g_attn_h[(size_t)MTOK * HID];
__device__ __half g_wqkv_h[(size_t)THID * HID];  // transposed [N][K]
__device__ __half g_wo_h  [(size_t)HID * HID];   // transposed [N][K], hi only

// ---------------------------- asm helpers -----------------------------------
__device__ __forceinline__ uint32_t smem_u32(const void* p) {
    uint32_t a;
    asm("{ .reg .u64 t; cvta.to.shared.u64 t, %1; cvt.u32.u64 %0, t; }" : "=r"(a) : "l"(p));
    return a;
}
#define CP16(dst, src)  asm volatile("cp.async.cg.shared.global [%0], [%1], 16;" :: "r"(dst), "l"(src) : "memory")
#define CP_COMMIT()     asm volatile("cp.async.commit_group;" ::: "memory")
#define CP_WAIT0()      asm volatile("cp.async.wait_group 0;" ::: "memory")
#define CP_WAIT1()      asm volatile("cp.async.wait_group 1;" ::: "memory")

#define LDSM4(r0,r1,r2,r3,addr)                                                \
    asm volatile("ldmatrix.sync.aligned.m8n8.x4.shared.b16 {%0,%1,%2,%3}, [%4];" \
        : "=r"(r0),"=r"(r1),"=r"(r2),"=r"(r3) : "r"(addr))

#define LDSM4T(r0,r1,r2,r3,addr)                                               \
    asm volatile("ldmatrix.sync.aligned.m8n8.x4.trans.shared.b16 {%0,%1,%2,%3}, [%4];" \
        : "=r"(r0),"=r"(r1),"=r"(r2),"=r"(r3) : "r"(addr))

#define MMA16816(c,a,b0,b1)                                                    \
    asm volatile("mma.sync.aligned.m16n8k16.row.col.f32.f16.f16.f32 "          \
        "{%0,%1,%2,%3},{%4,%5,%6,%7},{%8,%9},{%0,%1,%2,%3};"                   \
        : "+f"((c)[0]),"+f"((c)[1]),"+f"((c)[2]),"+f"((c)[3])                  \
        : "r"((a)[0]),"r"((a)[1]),"r"((a)[2]),"r"((a)[3]),"r"(b0),"r"(b1))

__device__ __forceinline__ uint32_t swz(int row, int g) {
    return (uint32_t)(row * 64 + ((g ^ ((row >> 1) & 3)) << 4));
}
__device__ __forceinline__ uint32_t vswz(int row, int g) {
    return (uint32_t)(row * 256 + ((g ^ (row & 7)) << 4));
}

// ---------------------------------------------------------------------------
__global__ __launch_bounds__(256) void convert_h(const float* __restrict__ in,
                                                 __half* __restrict__ hi, size_t n4) {
    size_t i = (size_t)blockIdx.x * blockDim.x + threadIdx.x;
    if (i >= n4) return;
    float4 v = ((const float4*)in)[i];
    __half h[4] = {__float2half(v.x), __float2half(v.y),
                   __float2half(v.z), __float2half(v.w)};
    ((uint2*)hi)[i] = *(uint2*)h;
}

// ---------------------------------------------------------------------------
// Transpose + fp16: B[K][N] fp32 -> Bt [N][K], hi only.
// ---------------------------------------------------------------------------
__global__ __launch_bounds__(256) void transpose_h(const float* __restrict__ B,
                                                   __half* __restrict__ th,
                                                   int K, int N) {
    __shared__ float tile[32][33];
    int n0 = blockIdx.x * 32, k0 = blockIdx.y * 32;
    int tx = threadIdx.x & 31, ty = threadIdx.x >> 5;
#pragma unroll
    for (int j = 0; j < 32; j += 8)
        tile[ty + j][tx] = B[(size_t)(k0 + ty + j) * N + n0 + tx];
    __syncthreads();
#pragma unroll
    for (int j = 0; j < 32; j += 8) {
        float x = tile[tx][ty + j];
        size_t o = (size_t)(n0 + ty + j) * K + k0 + tx;
        th[o] = __float2half(x);
    }
}

// ---------------------------------------------------------------------------
// fp16 GEMM on mma.sync (single pass: A fp16, B fp16).
// 128x128 CTA tile, BK=32, 4 stages x 16KB, 2 CTAs/SM.
// ---------------------------------------------------------------------------
#define BUFB  8192
#define STGB  (2 * BUFB)
#define NSTG  4
#define GEMM_DYN (NSTG * STGB)

__device__ __forceinline__ void stage_copies(int tid, int m0, int n0, int kc, int K,
                                             uint32_t sbase,
                                             const __half* Ah, const __half* Bh) {
#pragma unroll
    for (int i = 0; i < 4; i++) {
        int id  = tid + i * 256;
        int buf = id >> 9;
        int idx = id & 511;
        int row = idx >> 2;
        int g   = idx & 3;
        uint32_t dst = sbase + buf * BUFB + swz(row, g);
        const __half* src = (buf == 0) ? Ah + (size_t)(m0 + row) * K + kc + g * 8
                                       : Bh + (size_t)(n0 + row) * K + kc + g * 8;
        CP16(dst, src);
    }
    CP_COMMIT();
}

__global__ __launch_bounds__(256, 2) void gemm_mma_f16(
        const __half* __restrict__ Ah, const __half* __restrict__ Bh,
        float* __restrict__ C, int M, int N, int K) {
    extern __shared__ char dsm[];
    const uint32_t sb = smem_u32(dsm);
    const int tid  = threadIdx.x;
    const int lane = tid & 31;
    const int wid  = tid >> 5;
    const int m0 = blockIdx.y * 128, n0 = blockIdx.x * 128;
    const int wm = (wid >> 2) * 64;
    const int wn = (wid & 3) * 32;

    const int a_r  = lane & 15;
    const int a_g0 = lane >> 4;
    const int b_r  = (lane & 7) + ((lane >> 4) << 3);
    const int b_g0 = (lane >> 3) & 1;

    float acc[4][4][4];
#pragma unroll
    for (int i = 0; i < 4; i++)
#pragma unroll
        for (int j = 0; j < 4; j++)
#pragma unroll
            for (int r = 0; r < 4; r++) acc[i][j][r] = 0.f;

    const int NC = K / 32;
    stage_copies(tid, m0, n0, 0,  K, sb,            Ah, Bh);
    stage_copies(tid, m0, n0, 32, K, sb + STGB,     Ah, Bh);
    stage_copies(tid, m0, n0, 64, K, sb + 2 * STGB, Ah, Bh);

    uint32_t st = sb;
    for (int c = 0; c < NC; c++) {
        asm volatile("cp.async.wait_group 2;" ::: "memory");
        __syncthreads();
        if (c + 3 < NC)
            stage_copies(tid, m0, n0, (c + 3) * 32, K,
                         sb + ((c + 3) % NSTG) * STGB, Ah, Bh);
        else
            CP_COMMIT();

#pragma unroll
        for (int kk = 0; kk < 2; kk++) {
            const int gbase = kk * 2;
            uint32_t ah[4][4];
#pragma unroll
            for (int mf = 0; mf < 4; mf++) {
                uint32_t ad = st + swz(wm + mf * 16 + a_r, gbase + a_g0);
                LDSM4(ah[mf][0], ah[mf][1], ah[mf][2], ah[mf][3], ad);
            }
            uint32_t bh[4][2];
#pragma unroll
            for (int ng = 0; ng < 2; ng++) {
                uint32_t bd = st + BUFB + swz(wn + ng * 16 + b_r, gbase + b_g0);
                uint32_t t0, t1, t2, t3;
                LDSM4(t0, t1, t2, t3, bd);
                bh[2 * ng][0] = t0; bh[2 * ng][1] = t1;
                bh[2 * ng + 1][0] = t2; bh[2 * ng + 1][1] = t3;
            }
#pragma unroll
            for (int mf = 0; mf < 4; mf++)
#pragma unroll
                for (int nf = 0; nf < 4; nf++)
                    MMA16816(acc[mf][nf], ah[mf], bh[nf][0], bh[nf][1]);
        }
        st += STGB;
        if (st == sb + NSTG * STGB) st = sb;
    }

    const int fr = lane >> 2;
    const int fc = (lane & 3) * 2;
#pragma unroll
    for (int mf = 0; mf < 4; mf++) {
#pragma unroll
        for (int nf = 0; nf < 4; nf++) {
            float* p0 = C + (size_t)(m0 + wm + mf * 16 + fr) * N + n0 + wn + nf * 8 + fc;
            float* p1 = p0 + 8 * N;
            p0[0] = acc[mf][nf][0]; p0[1] = acc[mf][nf][1];
            p1[0] = acc[mf][nf][2]; p1[1] = acc[mf][nf][3];
        }
    }
}

// ---------------------------------------------------------------------------
// RoPE: read fp32 qkv, write fp16 q (scaled), k, v.
// ---------------------------------------------------------------------------
__global__ __launch_bounds__(256) void rope_kernel(const float* __restrict__ qkv,
                                                   const int* __restrict__ positions,
                                                   __half* __restrict__ qh,
                                                   __half* __restrict__ kh,
                                                   __half* __restrict__ vh) {
    int idx = blockIdx.x * blockDim.x + threadIdx.x;
    const int total = BB * SS * NH * HALF;
    if (idx >= total) return;
    int j = idx & 63;
    int h = (idx >> 6) & 31;
    int t = idx >> 11;
    int pos = positions[t];

    float inv_freq = powf(10000.0f, -(float)j / (float)HALF);
    float ang = (float)pos * inv_freq;
    float sn, cs;
    sincosf(ang, &sn, &cs);

    size_t base = (size_t)t * THID + h * HD;
    size_t obase = (size_t)t * HID + h * HD;
    {
        float x1 = qkv[base + j], x2 = qkv[base + HALF + j];
        qh[obase + j]        = __float2half((x1 * cs - x2 * sn) * SCALING);
        qh[obase + HALF + j] = __float2half((x2 * cs + x1 * sn) * SCALING);
    }
    {
        size_t kb = base + HID;
        float x1 = qkv[kb + j], x2 = qkv[kb + HALF + j];
        kh[obase + j]        = __float2half(x1 * cs - x2 * sn);
        kh[obase + HALF + j] = __float2half(x2 * cs + x1 * sn);
    }
    {
        size_t vb = base + 2 * HID;
        vh[obase + j]        = __float2half(qkv[vb + j]);
        vh[obase + HALF + j] = __float2half(qkv[vb + HALF + j]);
    }
}

// ---------------------------------------------------------------------------
// Flash attention on HMMA (unchanged from R8).
// ---------------------------------------------------------------------------
#define FSM_Q 0
#define FSM_K 16384
#define FSM_V 32768
#define FLASH_DYN 49152

__global__ __launch_bounds__(128, 3) void flash_hmma(const __half* __restrict__ qh,
                                                     const __half* __restrict__ kh,
                                                     const __half* __restrict__ vh,
                                                     __half* __restrict__ ah) {
    const int qt = blockIdx.x;
    const int h  = blockIdx.y;
    const int b  = blockIdx.z;

    extern __shared__ char dsm[];
    const uint32_t sb = smem_u32(dsm);
    const int tid  = threadIdx.x;
    const int lane = tid & 31;
    const int wid  = tid >> 5;
    const int fr = lane >> 2;
    const int qq = lane & 3;

    const int a_r  = lane & 15;
    const int a_gh = lane >> 4;
    const int b_r  = (lane & 7) + ((lane >> 4) << 3);
    const int b_gh = (lane >> 3) & 1;
    const int vk   = (lane & 7) + (((lane >> 3) & 1) << 3);
    const int vg   = lane >> 4;

#pragma unroll
    for (int i = 0; i < 8; i++) {
        int idx = tid + i * 128;
        int row = idx >> 4, g = idx & 15;
        const __half* src = qh + ((size_t)(b * SS + qt * 64 + row) * HID + h * HD + g * 8);
        CP16(sb + FSM_Q + vswz(row, g), src);
    }
    CP_COMMIT();

    float o[16][4];
#pragma unroll
    for (int i = 0; i < 16; i++)
#pragma unroll
        for (int r = 0; r < 4; r++) o[i][r] = 0.f;
    float m0 = -1e30f, m1 = -1e30f, l0 = 0.f, l1 = 0.f;

    for (int j = 0; j <= qt; j++) {
#pragma unroll
        for (int i = 0; i < 8; i++) {
            int idx = tid + i * 128;
            int row = idx >> 4, g = idx & 15;
            size_t srco = (size_t)(b * SS + j * 64 + row) * HID + h * HD + g * 8;
            CP16(sb + FSM_K + vswz(row, g), kh + srco);
            CP16(sb + FSM_V + vswz(row, g), vh + srco);
        }
        CP_COMMIT();
        CP_WAIT0();
        __syncthreads();

        float s[8][4];
#pragma unroll
        for (int nf = 0; nf < 8; nf++)
#pragma unroll
            for (int r = 0; r < 4; r++) s[nf][r] = 0.f;

#pragma unroll
        for (int ks = 0; ks < 8; ks++) {
            uint32_t aq[4];
            LDSM4(aq[0], aq[1], aq[2], aq[3],
                  sb + FSM_Q + vswz(wid * 16 + a_r, ks * 2 + a_gh));
#pragma unroll
            for (int np = 0; np < 4; np++) {
                uint32_t t0, t1, t2, t3;
                LDSM4(t0, t1, t2, t3, sb + FSM_K + vswz(np * 16 + b_r, ks * 2 + b_gh));
                MMA16816(s[np * 2],     aq, t0, t1);
                MMA16816(s[np * 2 + 1], aq, t2, t3);
            }
        }

        if (j == qt) {
            int row0 = wid * 16 + fr;
            int row1 = row0 + 8;
#pragma unroll
            for (int nf = 0; nf < 8; nf++) {
                int c0 = nf * 8 + qq * 2;
                if (c0 > row0)     s[nf][0] = -1e30f;
                if (c0 + 1 > row0) s[nf][1] = -1e30f;
                if (c0 > row1)     s[nf][2] = -1e30f;
                if (c0 + 1 > row1) s[nf][3] = -1e30f;
            }
        }

        float mx0 = -1e30f, mx1 = -1e30f;
#pragma unroll
        for (int nf = 0; nf < 8; nf++) {
            mx0 = fmaxf(mx0, fmaxf(s[nf][0], s[nf][1]));
            mx1 = fmaxf(mx1, fmaxf(s[nf][2], s[nf][3]));
        }
        mx0 = fmaxf(mx0, __shfl_xor_sync(0xffffffffu, mx0, 1));
        mx0 = fmaxf(mx0, __shfl_xor_sync(0xffffffffu, mx0, 2));
        mx1 = fmaxf(mx1, __shfl_xor_sync(0xffffffffu, mx1, 1));
        mx1 = fmaxf(mx1, __shfl_xor_sync(0xffffffffu, mx1, 2));

        float mn0 = fmaxf(m0, mx0), mn1 = fmaxf(m1, mx1);
        float f0 = __expf(m0 - mn0), f1 = __expf(m1 - mn1);
        m0 = mn0; m1 = mn1;

        uint32_t ph[8][2];
        float sum0 = 0.f, sum1 = 0.f;
#pragma unroll
        for (int nf = 0; nf < 8; nf++) {
            float p0 = __expf(s[nf][0] - m0);
            float p1 = __expf(s[nf][1] - m0);
            float p2 = __expf(s[nf][2] - m1);
            float p3 = __expf(s[nf][3] - m1);
            sum0 += p0 + p1; sum1 += p2 + p3;
            __half2 h01 = __floats2half2_rn(p0, p1);
            __half2 h23 = __floats2half2_rn(p2, p3);
            ph[nf][0] = *(uint32_t*)&h01;
            ph[nf][1] = *(uint32_t*)&h23;
        }
        sum0 += __shfl_xor_sync(0xffffffffu, sum0, 1);
        sum0 += __shfl_xor_sync(0xffffffffu, sum0, 2);
        sum1 += __shfl_xor_sync(0xffffffffu, sum1, 1);
        sum1 += __shfl_xor_sync(0xffffffffu, sum1, 2);
        l0 = l0 * f0 + sum0;
        l1 = l1 * f1 + sum1;

#pragma unroll
        for (int i = 0; i < 16; i++) {
            o[i][0] *= f0; o[i][1] *= f0;
            o[i][2] *= f1; o[i][3] *= f1;
        }

#pragma unroll
        for (int ks = 0; ks < 4; ks++) {
            uint32_t ap[4] = {ph[2 * ks][0], ph[2 * ks][1],
                              ph[2 * ks + 1][0], ph[2 * ks + 1][1]};
#pragma unroll
            for (int np = 0; np < 8; np++) {
                uint32_t t0, t1, t2, t3;
                LDSM4T(t0, t1, t2, t3, sb + FSM_V + vswz(ks * 16 + vk, np * 2 + vg));
                MMA16816(o[np * 2],     ap, t0, t1);
                MMA16816(o[np * 2 + 1], ap, t2, t3);
            }
        }
        __syncthreads();
    }

    float inv0 = 1.f / l0, inv1 = 1.f / l1;
    int row0 = b * SS + qt * 64 + wid * 16 + fr;
#pragma unroll
    for (int np = 0; np < 16; np++) {
        int col = h * HD + np * 8 + qq * 2;
        __half2 v0 = __floats2half2_rn(o[np][0] * inv0, o[np][1] * inv0);
        __half2 v1 = __floats2half2_rn(o[np][2] * inv1, o[np][3] * inv1);
        *(__half2*)(ah + (size_t)row0 * HID + col) = v0;
        *(__half2*)(ah + (size_t)(row0 + 8) * HID + col) = v1;
    }
}

// ---------------------------------------------------------------------------
extern "C" void kernel_launch(void* const* d_in, const int* in_sizes, int n_in,
                              void* d_out, int out_size) {
    const int*   positions = (const int*)  d_in[0];
    const float* hidden    = (const float*)d_in[1];
    const float* Wqkv      = (const float*)d_in[2];
    const float* Wo        = (const float*)d_in[3];
    float* out = (float*)d_out;

    float *qkv;
    __half *hh, *ah, *qh, *oh, *qhx, *khx, *vhx;
    cudaGetSymbolAddress((void**)&qkv, g_qkv);
    cudaGetSymbolAddress((void**)&hh, g_hid_h);
    cudaGetSymbolAddress((void**)&ah, g_attn_h);
    cudaGetSymbolAddress((void**)&qh, g_wqkv_h);
    cudaGetSymbolAddress((void**)&oh, g_wo_h);
    cudaGetSymbolAddress((void**)&qhx, g_q_h);
    cudaGetSymbolAddress((void**)&khx, g_k_h);
    cudaGetSymbolAddress((void**)&vhx, g_v_h);

    cudaFuncSetAttribute(gemm_mma_f16,
                         cudaFuncAttributeMaxDynamicSharedMemorySize, GEMM_DYN);
    cudaFuncSetAttribute(flash_hmma,
                         cudaFuncAttributeMaxDynamicSharedMemorySize, FLASH_DYN);

    {
        size_t n4 = (size_t)MTOK * HID / 4;
        convert_h<<<(unsigned)((n4 + 255) / 256), 256>>>(hidden, hh, n4);
    }
    transpose_h<<<dim3(THID / 32, HID / 32), 256>>>(Wqkv, qh, HID, THID);
    gemm_mma_f16<<<dim3(THID / 128, MTOK / 128), 256, GEMM_DYN>>>(hh, qh, qkv,
                                                                  MTOK, THID, HID);
    {
        int total = BB * SS * NH * HALF;
        rope_kernel<<<(total + 255) / 256, 256>>>(qkv, positions, qhx, khx, vhx);
    }
    flash_hmma<<<dim3(SS / 64, NH, BB), 128, FLASH_DYN>>>(qhx, khx, vhx, ah);
    transpose_h<<<dim3(HID / 32, HID / 32), 256>>>(Wo, oh, HID, HID);
    gemm_mma_f16<<<dim3(HID / 128, MTOK / 128), 256, GEMM_DYN>>>(ah, oh, out,
                                                                 MTOK, HID, HID);
}

// round 10
// speedup vs baseline: 8.4578x; 1.0245x over previous
#include <cuda_runtime.h>
#include <cuda_fp16.h>
#include <math.h>
#include <stdint.h>

#define HID   4096
#define NH    32
#define HD    128
#define HALF  64
#define BB    2
#define SS    2048
#define THID  12288
#define MTOK  (BB*SS)
#define SCALING 0.08838834764831845f

// ---------------- scratch ----------------------------------------------------
__device__ __half g_qkv_h[(size_t)MTOK * THID];  // fp16 qkv (q|k|v), GEMM output
__device__ __half g_q_h [(size_t)MTOK * HID];    // rope'd q * SCALING
__device__ __half g_k_h [(size_t)MTOK * HID];    // rope'd k
__device__ __half g_hid_h [(size_t)MTOK * HID];
__device__ __half g_attn_h[(size_t)MTOK * HID];
__device__ __half g_wqkv_h[(size_t)THID * HID];  // transposed [N][K]
__device__ __half g_wo_h  [(size_t)HID * HID];   // transposed [N][K]

// ---------------------------- asm helpers -----------------------------------
__device__ __forceinline__ uint32_t smem_u32(const void* p) {
    uint32_t a;
    asm("{ .reg .u64 t; cvta.to.shared.u64 t, %1; cvt.u32.u64 %0, t; }" : "=r"(a) : "l"(p));
    return a;
}
#define CP16(dst, src)  asm volatile("cp.async.cg.shared.global [%0], [%1], 16;" :: "r"(dst), "l"(src) : "memory")
#define CP_COMMIT()     asm volatile("cp.async.commit_group;" ::: "memory")
#define CP_WAIT0()      asm volatile("cp.async.wait_group 0;" ::: "memory")
#define CP_WAIT1()      asm volatile("cp.async.wait_group 1;" ::: "memory")

#define LDSM4(r0,r1,r2,r3,addr)                                                \
    asm volatile("ldmatrix.sync.aligned.m8n8.x4.shared.b16 {%0,%1,%2,%3}, [%4];" \
        : "=r"(r0),"=r"(r1),"=r"(r2),"=r"(r3) : "r"(addr))

#define LDSM4T(r0,r1,r2,r3,addr)                                               \
    asm volatile("ldmatrix.sync.aligned.m8n8.x4.trans.shared.b16 {%0,%1,%2,%3}, [%4];" \
        : "=r"(r0),"=r"(r1),"=r"(r2),"=r"(r3) : "r"(addr))

#define MMA16816(c,a,b0,b1)                                                    \
    asm volatile("mma.sync.aligned.m16n8k16.row.col.f32.f16.f16.f32 "          \
        "{%0,%1,%2,%3},{%4,%5,%6,%7},{%8,%9},{%0,%1,%2,%3};"                   \
        : "+f"((c)[0]),"+f"((c)[1]),"+f"((c)[2]),"+f"((c)[3])                  \
        : "r"((a)[0]),"r"((a)[1]),"r"((a)[2]),"r"((a)[3]),"r"(b0),"r"(b1))

// 128B-row swizzle (8 x 16B granules, XOR with row&7): conflict-free for
// cp.async writes, ldmatrix and ldmatrix.trans reads.
__device__ __forceinline__ uint32_t gswz(int row, int g) {
    return (uint32_t)(row * 128 + ((g ^ (row & 7)) << 4));
}
// 256B-row variant for the flash 64x128 tiles.
__device__ __forceinline__ uint32_t vswz(int row, int g) {
    return (uint32_t)(row * 256 + ((g ^ (row & 7)) << 4));
}

// ---------------------------------------------------------------------------
__global__ __launch_bounds__(256) void convert_h(const float* __restrict__ in,
                                                 __half* __restrict__ hi, size_t n4) {
    size_t i = (size_t)blockIdx.x * blockDim.x + threadIdx.x;
    if (i >= n4) return;
    float4 v = ((const float4*)in)[i];
    __half h[4] = {__float2half(v.x), __float2half(v.y),
                   __float2half(v.z), __float2half(v.w)};
    ((uint2*)hi)[i] = *(uint2*)h;
}

// ---------------------------------------------------------------------------
// Transpose + fp16: B[K][N] fp32 -> Bt [N][K]
// ---------------------------------------------------------------------------
__global__ __launch_bounds__(256) void transpose_h(const float* __restrict__ B,
                                                   __half* __restrict__ th,
                                                   int K, int N) {
    __shared__ float tile[32][33];
    int n0 = blockIdx.x * 32, k0 = blockIdx.y * 32;
    int tx = threadIdx.x & 31, ty = threadIdx.x >> 5;
#pragma unroll
    for (int j = 0; j < 32; j += 8)
        tile[ty + j][tx] = B[(size_t)(k0 + ty + j) * N + n0 + tx];
    __syncthreads();
#pragma unroll
    for (int j = 0; j < 32; j += 8) {
        float x = tile[tx][ty + j];
        size_t o = (size_t)(n0 + ty + j) * K + k0 + tx;
        th[o] = __float2half(x);
    }
}

// ---------------------------------------------------------------------------
// fp16 GEMM on mma.sync. 128x128 CTA tile, BK=64, 3 stages x 32KB, 2 CTAs/SM.
// Templated output type (fp16 for QKV, fp32 for final O-proj).
// ---------------------------------------------------------------------------
#define BUFB  16384                // 128 rows x 128B
#define STGB  (2 * BUFB)
#define NSTG  3
#define GEMM_DYN (NSTG * STGB)

__device__ __forceinline__ void stage_copies(int tid, int m0, int n0, int kc, int K,
                                             uint32_t sbase,
                                             const __half* Ah, const __half* Bh) {
#pragma unroll
    for (int i = 0; i < 8; i++) {
        int id  = tid + i * 256;       // 0..2047
        int buf = id >> 10;            // 0..1
        int idx = id & 1023;
        int row = idx >> 3;            // 0..127
        int g   = idx & 7;
        uint32_t dst = sbase + buf * BUFB + gswz(row, g);
        const __half* src = (buf == 0) ? Ah + (size_t)(m0 + row) * K + kc + g * 8
                                       : Bh + (size_t)(n0 + row) * K + kc + g * 8;
        CP16(dst, src);
    }
    CP_COMMIT();
}

template <typename CT>
__global__ __launch_bounds__(256, 2) void gemm_mma_f16(
        const __half* __restrict__ Ah, const __half* __restrict__ Bh,
        CT* __restrict__ C, int M, int N, int K) {
    extern __shared__ char dsm[];
    const uint32_t sb = smem_u32(dsm);
    const int tid  = threadIdx.x;
    const int lane = tid & 31;
    const int wid  = tid >> 5;
    const int m0 = blockIdx.y * 128, n0 = blockIdx.x * 128;
    const int wm = (wid >> 2) * 64;
    const int wn = (wid & 3) * 32;

    const int a_r  = lane & 15;
    const int a_g0 = lane >> 4;
    const int b_r  = (lane & 7) + ((lane >> 4) << 3);
    const int b_g0 = (lane >> 3) & 1;

    float acc[4][4][4];
#pragma unroll
    for (int i = 0; i < 4; i++)
#pragma unroll
        for (int j = 0; j < 4; j++)
#pragma unroll
            for (int r = 0; r < 4; r++) acc[i][j][r] = 0.f;

    const int NC = K / 64;
    stage_copies(tid, m0, n0, 0,  K, sb,        Ah, Bh);
    stage_copies(tid, m0, n0, 64, K, sb + STGB, Ah, Bh);

    uint32_t st = sb;
    for (int c = 0; c < NC; c++) {
        CP_WAIT1();
        __syncthreads();
        if (c + 2 < NC)
            stage_copies(tid, m0, n0, (c + 2) * 64, K,
                         sb + ((c + 2) % NSTG) * STGB, Ah, Bh);
        else
            CP_COMMIT();

#pragma unroll
        for (int kk = 0; kk < 4; kk++) {
            const int gbase = kk * 2;
            uint32_t ah[4][4];
#pragma unroll
            for (int mf = 0; mf < 4; mf++) {
                uint32_t ad = st + gswz(wm + mf * 16 + a_r, gbase + a_g0);
                LDSM4(ah[mf][0], ah[mf][1], ah[mf][2], ah[mf][3], ad);
            }
            uint32_t bh[4][2];
#pragma unroll
            for (int ng = 0; ng < 2; ng++) {
                uint32_t bd = st + BUFB + gswz(wn + ng * 16 + b_r, gbase + b_g0);
                uint32_t t0, t1, t2, t3;
                LDSM4(t0, t1, t2, t3, bd);
                bh[2 * ng][0] = t0; bh[2 * ng][1] = t1;
                bh[2 * ng + 1][0] = t2; bh[2 * ng + 1][1] = t3;
            }
#pragma unroll
            for (int mf = 0; mf < 4; mf++)
#pragma unroll
                for (int nf = 0; nf < 4; nf++)
                    MMA16816(acc[mf][nf], ah[mf], bh[nf][0], bh[nf][1]);
        }
        st += STGB;
        if (st == sb + NSTG * STGB) st = sb;
    }

    const int fr = lane >> 2;
    const int fc = (lane & 3) * 2;
#pragma unroll
    for (int mf = 0; mf < 4; mf++) {
#pragma unroll
        for (int nf = 0; nf < 4; nf++) {
            CT* p0 = C + (size_t)(m0 + wm + mf * 16 + fr) * N + n0 + wn + nf * 8 + fc;
            CT* p1 = p0 + 8 * N;
            if (sizeof(CT) == 2) {
                __half2 h0 = __floats2half2_rn(acc[mf][nf][0], acc[mf][nf][1]);
                __half2 h1 = __floats2half2_rn(acc[mf][nf][2], acc[mf][nf][3]);
                *(__half2*)p0 = h0;
                *(__half2*)p1 = h1;
            } else {
                p0[0] = (CT)acc[mf][nf][0]; p0[1] = (CT)acc[mf][nf][1];
                p1[0] = (CT)acc[mf][nf][2]; p1[1] = (CT)acc[mf][nf][3];
            }
        }
    }
}

// ---------------------------------------------------------------------------
// RoPE on fp16 qkv: writes rope'd q (scaled) and k; v stays in qkv buffer.
// ---------------------------------------------------------------------------
__global__ __launch_bounds__(256) void rope_kernel(const __half* __restrict__ qkv,
                                                   const int* __restrict__ positions,
                                                   __half* __restrict__ qh,
                                                   __half* __restrict__ kh) {
    int idx = blockIdx.x * blockDim.x + threadIdx.x;
    const int total = BB * SS * NH * HALF;
    if (idx >= total) return;
    int j = idx & 63;
    int h = (idx >> 6) & 31;
    int t = idx >> 11;
    int pos = positions[t];

    float inv_freq = powf(10000.0f, -(float)j / (float)HALF);
    float ang = (float)pos * inv_freq;
    float sn, cs;
    sincosf(ang, &sn, &cs);

    size_t base = (size_t)t * THID + h * HD;
    size_t obase = (size_t)t * HID + h * HD;
    {
        float x1 = __half2float(qkv[base + j]);
        float x2 = __half2float(qkv[base + HALF + j]);
        qh[obase + j]        = __float2half((x1 * cs - x2 * sn) * SCALING);
        qh[obase + HALF + j] = __float2half((x2 * cs + x1 * sn) * SCALING);
    }
    {
        size_t kb = base + HID;
        float x1 = __half2float(qkv[kb + j]);
        float x2 = __half2float(qkv[kb + HALF + j]);
        kh[obase + j]        = __float2half(x1 * cs - x2 * sn);
        kh[obase + HALF + j] = __float2half(x2 * cs + x1 * sn);
    }
}

// ---------------------------------------------------------------------------
// Flash attention on HMMA. V read directly from fp16 qkv (stride THID).
// ---------------------------------------------------------------------------
#define FSM_Q 0
#define FSM_K 16384
#define FSM_V 32768
#define FLASH_DYN 49152

__global__ __launch_bounds__(128, 3) void flash_hmma(const __half* __restrict__ qh,
                                                     const __half* __restrict__ kh,
                                                     const __half* __restrict__ qkvh,
                                                     __half* __restrict__ ah) {
    const int qt = blockIdx.x;
    const int h  = blockIdx.y;
    const int b  = blockIdx.z;

    extern __shared__ char dsm[];
    const uint32_t sb = smem_u32(dsm);
    const int tid  = threadIdx.x;
    const int lane = tid & 31;
    const int wid  = tid >> 5;
    const int fr = lane >> 2;
    const int qq = lane & 3;

    const int a_r  = lane & 15;
    const int a_gh = lane >> 4;
    const int b_r  = (lane & 7) + ((lane >> 4) << 3);
    const int b_gh = (lane >> 3) & 1;
    const int vk   = (lane & 7) + (((lane >> 3) & 1) << 3);
    const int vg   = lane >> 4;

#pragma unroll
    for (int i = 0; i < 8; i++) {
        int idx = tid + i * 128;
        int row = idx >> 4, g = idx & 15;
        const __half* src = qh + ((size_t)(b * SS + qt * 64 + row) * HID + h * HD + g * 8);
        CP16(sb + FSM_Q + vswz(row, g), src);
    }
    CP_COMMIT();

    float o[16][4];
#pragma unroll
    for (int i = 0; i < 16; i++)
#pragma unroll
        for (int r = 0; r < 4; r++) o[i][r] = 0.f;
    float m0 = -1e30f, m1 = -1e30f, l0 = 0.f, l1 = 0.f;

    for (int j = 0; j <= qt; j++) {
#pragma unroll
        for (int i = 0; i < 8; i++) {
            int idx = tid + i * 128;
            int row = idx >> 4, g = idx & 15;
            int tok = b * SS + j * 64 + row;
            CP16(sb + FSM_K + vswz(row, g),
                 kh + ((size_t)tok * HID + h * HD + g * 8));
            CP16(sb + FSM_V + vswz(row, g),
                 qkvh + ((size_t)tok * THID + 2 * HID + h * HD + g * 8));
        }
        CP_COMMIT();
        CP_WAIT0();
        __syncthreads();

        float s[8][4];
#pragma unroll
        for (int nf = 0; nf < 8; nf++)
#pragma unroll
            for (int r = 0; r < 4; r++) s[nf][r] = 0.f;

#pragma unroll
        for (int ks = 0; ks < 8; ks++) {
            uint32_t aq[4];
            LDSM4(aq[0], aq[1], aq[2], aq[3],
                  sb + FSM_Q + vswz(wid * 16 + a_r, ks * 2 + a_gh));
#pragma unroll
            for (int np = 0; np < 4; np++) {
                uint32_t t0, t1, t2, t3;
                LDSM4(t0, t1, t2, t3, sb + FSM_K + vswz(np * 16 + b_r, ks * 2 + b_gh));
                MMA16816(s[np * 2],     aq, t0, t1);
                MMA16816(s[np * 2 + 1], aq, t2, t3);
            }
        }

        if (j == qt) {
            int row0 = wid * 16 + fr;
            int row1 = row0 + 8;
#pragma unroll
            for (int nf = 0; nf < 8; nf++) {
                int c0 = nf * 8 + qq * 2;
                if (c0 > row0)     s[nf][0] = -1e30f;
                if (c0 + 1 > row0) s[nf][1] = -1e30f;
                if (c0 > row1)     s[nf][2] = -1e30f;
                if (c0 + 1 > row1) s[nf][3] = -1e30f;
            }
        }

        float mx0 = -1e30f, mx1 = -1e30f;
#pragma unroll
        for (int nf = 0; nf < 8; nf++) {
            mx0 = fmaxf(mx0, fmaxf(s[nf][0], s[nf][1]));
            mx1 = fmaxf(mx1, fmaxf(s[nf][2], s[nf][3]));
        }
        mx0 = fmaxf(mx0, __shfl_xor_sync(0xffffffffu, mx0, 1));
        mx0 = fmaxf(mx0, __shfl_xor_sync(0xffffffffu, mx0, 2));
        mx1 = fmaxf(mx1, __shfl_xor_sync(0xffffffffu, mx1, 1));
        mx1 = fmaxf(mx1, __shfl_xor_sync(0xffffffffu, mx1, 2));

        float mn0 = fmaxf(m0, mx0), mn1 = fmaxf(m1, mx1);
        float f0 = __expf(m0 - mn0), f1 = __expf(m1 - mn1);
        m0 = mn0; m1 = mn1;

        uint32_t ph[8][2];
        float sum0 = 0.f, sum1 = 0.f;
#pragma unroll
        for (int nf = 0; nf < 8; nf++) {
            float p0 = __expf(s[nf][0] - m0);
            float p1 = __expf(s[nf][1] - m0);
            float p2 = __expf(s[nf][2] - m1);
            float p3 = __expf(s[nf][3] - m1);
            sum0 += p0 + p1; sum1 += p2 + p3;
            __half2 h01 = __floats2half2_rn(p0, p1);
            __half2 h23 = __floats2half2_rn(p2, p3);
            ph[nf][0] = *(uint32_t*)&h01;
            ph[nf][1] = *(uint32_t*)&h23;
        }
        sum0 += __shfl_xor_sync(0xffffffffu, sum0, 1);
        sum0 += __shfl_xor_sync(0xffffffffu, sum0, 2);
        sum1 += __shfl_xor_sync(0xffffffffu, sum1, 1);
        sum1 += __shfl_xor_sync(0xffffffffu, sum1, 2);
        l0 = l0 * f0 + sum0;
        l1 = l1 * f1 + sum1;

#pragma unroll
        for (int i = 0; i < 16; i++) {
            o[i][0] *= f0; o[i][1] *= f0;
            o[i][2] *= f1; o[i][3] *= f1;
        }

#pragma unroll
        for (int ks = 0; ks < 4; ks++) {
            uint32_t ap[4] = {ph[2 * ks][0], ph[2 * ks][1],
                              ph[2 * ks + 1][0], ph[2 * ks + 1][1]};
#pragma unroll
            for (int np = 0; np < 8; np++) {
                uint32_t t0, t1, t2, t3;
                LDSM4T(t0, t1, t2, t3, sb + FSM_V + vswz(ks * 16 + vk, np * 2 + vg));
                MMA16816(o[np * 2],     ap, t0, t1);
                MMA16816(o[np * 2 + 1], ap, t2, t3);
            }
        }
        __syncthreads();
    }

    float inv0 = 1.f / l0, inv1 = 1.f / l1;
    int row0 = b * SS + qt * 64 + wid * 16 + fr;
#pragma unroll
    for (int np = 0; np < 16; np++) {
        int col = h * HD + np * 8 + qq * 2;
        __half2 v0 = __floats2half2_rn(o[np][0] * inv0, o[np][1] * inv0);
        __half2 v1 = __floats2half2_rn(o[np][2] * inv1, o[np][3] * inv1);
        *(__half2*)(ah + (size_t)row0 * HID + col) = v0;
        *(__half2*)(ah + (size_t)(row0 + 8) * HID + col) = v1;
    }
}

// ---------------------------------------------------------------------------
extern "C" void kernel_launch(void* const* d_in, const int* in_sizes, int n_in,
                              void* d_out, int out_size) {
    const int*   positions = (const int*)  d_in[0];
    const float* hidden    = (const float*)d_in[1];
    const float* Wqkv      = (const float*)d_in[2];
    const float* Wo        = (const float*)d_in[3];
    float* out = (float*)d_out;

    __half *qkvh, *hh, *ah, *qh, *oh, *qhx, *khx;
    cudaGetSymbolAddress((void**)&qkvh, g_qkv_h);
    cudaGetSymbolAddress((void**)&hh, g_hid_h);
    cudaGetSymbolAddress((void**)&ah, g_attn_h);
    cudaGetSymbolAddress((void**)&qh, g_wqkv_h);
    cudaGetSymbolAddress((void**)&oh, g_wo_h);
    cudaGetSymbolAddress((void**)&qhx, g_q_h);
    cudaGetSymbolAddress((void**)&khx, g_k_h);

    cudaFuncSetAttribute(gemm_mma_f16<__half>,
                         cudaFuncAttributeMaxDynamicSharedMemorySize, GEMM_DYN);
    cudaFuncSetAttribute(gemm_mma_f16<float>,
                         cudaFuncAttributeMaxDynamicSharedMemorySize, GEMM_DYN);
    cudaFuncSetAttribute(flash_hmma,
                         cudaFuncAttributeMaxDynamicSharedMemorySize, FLASH_DYN);

    {
        size_t n4 = (size_t)MTOK * HID / 4;
        convert_h<<<(unsigned)((n4 + 255) / 256), 256>>>(hidden, hh, n4);
    }
    transpose_h<<<dim3(THID / 32, HID / 32), 256>>>(Wqkv, qh, HID, THID);
    gemm_mma_f16<__half><<<dim3(THID / 128, MTOK / 128), 256, GEMM_DYN>>>(
        hh, qh, qkvh, MTOK, THID, HID);
    {
        int total = BB * SS * NH * HALF;
        rope_kernel<<<(total + 255) / 256, 256>>>(qkvh, positions, qhx, khx);
    }
    flash_hmma<<<dim3(SS / 64, NH, BB), 128, FLASH_DYN>>>(qhx, khx, qkvh, ah);
    transpose_h<<<dim3(HID / 32, HID / 32), 256>>>(Wo, oh, HID, HID);
    gemm_mma_f16<float><<<dim3(HID / 128, MTOK / 128), 256, GEMM_DYN>>>(
        ah, oh, out, MTOK, HID, HID);
}

// round 11
// speedup vs baseline: 8.4899x; 1.0038x over previous
#include <cuda_runtime.h>
#include <cuda_fp16.h>
#include <math.h>
#include <stdint.h>

#define HID   4096
#define NH    32
#define HD    128
#define HALF  64
#define BB    2
#define SS    2048
#define THID  12288
#define MTOK  (BB*SS)
#define SCALING 0.08838834764831845f

// ---------------- scratch ----------------------------------------------------
__device__ __half g_qkv_h[(size_t)MTOK * THID];  // fp16 qkv (q|k|v), GEMM output
__device__ __half g_q_h [(size_t)MTOK * HID];    // rope'd q * SCALING
__device__ __half g_k_h [(size_t)MTOK * HID];    // rope'd k
__device__ __half g_hid_h [(size_t)MTOK * HID];
__device__ __half g_attn_h[(size_t)MTOK * HID];
__device__ __half g_wqkv_h[(size_t)THID * HID];  // transposed [N][K]
__device__ __half g_wo_h  [(size_t)HID * HID];   // transposed [N][K]

// ---------------------------- asm helpers -----------------------------------
__device__ __forceinline__ uint32_t smem_u32(const void* p) {
    uint32_t a;
    asm("{ .reg .u64 t; cvta.to.shared.u64 t, %1; cvt.u32.u64 %0, t; }" : "=r"(a) : "l"(p));
    return a;
}
#define CP16(dst, src)  asm volatile("cp.async.cg.shared.global [%0], [%1], 16;" :: "r"(dst), "l"(src) : "memory")
#define CP_COMMIT()     asm volatile("cp.async.commit_group;" ::: "memory")
#define CP_WAIT0()      asm volatile("cp.async.wait_group 0;" ::: "memory")
#define CP_WAIT1()      asm volatile("cp.async.wait_group 1;" ::: "memory")

#define LDSM4(r0,r1,r2,r3,addr)                                                \
    asm volatile("ldmatrix.sync.aligned.m8n8.x4.shared.b16 {%0,%1,%2,%3}, [%4];" \
        : "=r"(r0),"=r"(r1),"=r"(r2),"=r"(r3) : "r"(addr))

#define LDSM4T(r0,r1,r2,r3,addr)                                               \
    asm volatile("ldmatrix.sync.aligned.m8n8.x4.trans.shared.b16 {%0,%1,%2,%3}, [%4];" \
        : "=r"(r0),"=r"(r1),"=r"(r2),"=r"(r3) : "r"(addr))

#define MMA16816(c,a,b0,b1)                                                    \
    asm volatile("mma.sync.aligned.m16n8k16.row.col.f32.f16.f16.f32 "          \
        "{%0,%1,%2,%3},{%4,%5,%6,%7},{%8,%9},{%0,%1,%2,%3};"                   \
        : "+f"((c)[0]),"+f"((c)[1]),"+f"((c)[2]),"+f"((c)[3])                  \
        : "r"((a)[0]),"r"((a)[1]),"r"((a)[2]),"r"((a)[3]),"r"(b0),"r"(b1))

// 128B-row swizzle (8 x 16B granules, XOR with row&7)
__device__ __forceinline__ uint32_t gswz(int row, int g) {
    return (uint32_t)(row * 128 + ((g ^ (row & 7)) << 4));
}
// 256B-row variant for the flash 64x128 tiles.
__device__ __forceinline__ uint32_t vswz(int row, int g) {
    return (uint32_t)(row * 256 + ((g ^ (row & 7)) << 4));
}

// ---------------------------------------------------------------------------
__global__ __launch_bounds__(256) void convert_h(const float* __restrict__ in,
                                                 __half* __restrict__ hi, size_t n4) {
    size_t i = (size_t)blockIdx.x * blockDim.x + threadIdx.x;
    if (i >= n4) return;
    float4 v = ((const float4*)in)[i];
    __half h[4] = {__float2half(v.x), __float2half(v.y),
                   __float2half(v.z), __float2half(v.w)};
    ((uint2*)hi)[i] = *(uint2*)h;
}

// ---------------------------------------------------------------------------
// Transpose + fp16: B[K][N] fp32 -> Bt [N][K]
// ---------------------------------------------------------------------------
__global__ __launch_bounds__(256) void transpose_h(const float* __restrict__ B,
                                                   __half* __restrict__ th,
                                                   int K, int N) {
    __shared__ float tile[32][33];
    int n0 = blockIdx.x * 32, k0 = blockIdx.y * 32;
    int tx = threadIdx.x & 31, ty = threadIdx.x >> 5;
#pragma unroll
    for (int j = 0; j < 32; j += 8)
        tile[ty + j][tx] = B[(size_t)(k0 + ty + j) * N + n0 + tx];
    __syncthreads();
#pragma unroll
    for (int j = 0; j < 32; j += 8) {
        float x = tile[tx][ty + j];
        size_t o = (size_t)(n0 + ty + j) * K + k0 + tx;
        th[o] = __float2half(x);
    }
}

// ---------------------------------------------------------------------------
// Persistent fp16 GEMM on mma.sync. 128x128 tiles, BK=64, 3 stages x 32KB,
// 2 CTAs/SM, grid-stride tile loop (no wave-quantization tail).
// ---------------------------------------------------------------------------
#define BUFB  16384                // 128 rows x 128B
#define STGB  (2 * BUFB)
#define NSTG  3
#define GEMM_DYN (NSTG * STGB)

__device__ __forceinline__ void stage_copies(int tid, int m0, int n0, int kc, int K,
                                             uint32_t sbase,
                                             const __half* Ah, const __half* Bh) {
#pragma unroll
    for (int i = 0; i < 8; i++) {
        int id  = tid + i * 256;       // 0..2047
        int buf = id >> 10;            // 0..1
        int idx = id & 1023;
        int row = idx >> 3;            // 0..127
        int g   = idx & 7;
        uint32_t dst = sbase + buf * BUFB + gswz(row, g);
        const __half* src = (buf == 0) ? Ah + (size_t)(m0 + row) * K + kc + g * 8
                                       : Bh + (size_t)(n0 + row) * K + kc + g * 8;
        CP16(dst, src);
    }
    CP_COMMIT();
}

template <typename CT>
__global__ __launch_bounds__(256, 2) void gemm_mma_f16(
        const __half* __restrict__ Ah, const __half* __restrict__ Bh,
        CT* __restrict__ C, int M, int N, int K) {
    extern __shared__ char dsm[];
    const uint32_t sb = smem_u32(dsm);
    const int tid  = threadIdx.x;
    const int lane = tid & 31;
    const int wid  = tid >> 5;
    const int wm = (wid >> 2) * 64;
    const int wn = (wid & 3) * 32;

    const int a_r  = lane & 15;
    const int a_g0 = lane >> 4;
    const int b_r  = (lane & 7) + ((lane >> 4) << 3);
    const int b_g0 = (lane >> 3) & 1;
    const int fr = lane >> 2;
    const int fc = (lane & 3) * 2;

    const int ntn = N >> 7;
    const int ntiles = (M >> 7) * ntn;
    const int NC = K / 64;

    for (int t = blockIdx.x; t < ntiles; t += gridDim.x) {
        const int m0 = (t / ntn) << 7;
        const int n0 = (t % ntn) << 7;

        float acc[4][4][4];
#pragma unroll
        for (int i = 0; i < 4; i++)
#pragma unroll
            for (int j = 0; j < 4; j++)
#pragma unroll
                for (int r = 0; r < 4; r++) acc[i][j][r] = 0.f;

        stage_copies(tid, m0, n0, 0,  K, sb,        Ah, Bh);
        stage_copies(tid, m0, n0, 64, K, sb + STGB, Ah, Bh);

        uint32_t st = sb;
        for (int c = 0; c < NC; c++) {
            CP_WAIT1();
            __syncthreads();
            if (c + 2 < NC)
                stage_copies(tid, m0, n0, (c + 2) * 64, K,
                             sb + ((c + 2) % NSTG) * STGB, Ah, Bh);
            else
                CP_COMMIT();

#pragma unroll
            for (int kk = 0; kk < 4; kk++) {
                const int gbase = kk * 2;
                uint32_t ah[4][4];
#pragma unroll
                for (int mf = 0; mf < 4; mf++) {
                    uint32_t ad = st + gswz(wm + mf * 16 + a_r, gbase + a_g0);
                    LDSM4(ah[mf][0], ah[mf][1], ah[mf][2], ah[mf][3], ad);
                }
                uint32_t bh[4][2];
#pragma unroll
                for (int ng = 0; ng < 2; ng++) {
                    uint32_t bd = st + BUFB + gswz(wn + ng * 16 + b_r, gbase + b_g0);
                    uint32_t t0, t1, t2, t3;
                    LDSM4(t0, t1, t2, t3, bd);
                    bh[2 * ng][0] = t0; bh[2 * ng][1] = t1;
                    bh[2 * ng + 1][0] = t2; bh[2 * ng + 1][1] = t3;
                }
#pragma unroll
                for (int mf = 0; mf < 4; mf++)
#pragma unroll
                    for (int nf = 0; nf < 4; nf++)
                        MMA16816(acc[mf][nf], ah[mf], bh[nf][0], bh[nf][1]);
            }
            st += STGB;
            if (st == sb + NSTG * STGB) st = sb;
        }

        // epilogue
#pragma unroll
        for (int mf = 0; mf < 4; mf++) {
#pragma unroll
            for (int nf = 0; nf < 4; nf++) {
                CT* p0 = C + (size_t)(m0 + wm + mf * 16 + fr) * N + n0 + wn + nf * 8 + fc;
                CT* p1 = p0 + 8 * N;
                if (sizeof(CT) == 2) {
                    __half2 h0 = __floats2half2_rn(acc[mf][nf][0], acc[mf][nf][1]);
                    __half2 h1 = __floats2half2_rn(acc[mf][nf][2], acc[mf][nf][3]);
                    *(__half2*)p0 = h0;
                    *(__half2*)p1 = h1;
                } else {
                    p0[0] = (CT)acc[mf][nf][0]; p0[1] = (CT)acc[mf][nf][1];
                    p1[0] = (CT)acc[mf][nf][2]; p1[1] = (CT)acc[mf][nf][3];
                }
            }
        }
        __syncthreads();   // protect stage buffers from next tile's prologue
    }
}

// ---------------------------------------------------------------------------
// RoPE on fp16 qkv (fast-math): writes rope'd q (scaled) and k.
// ---------------------------------------------------------------------------
#define LN1E4_OVER_64 0.14391156f   // ln(10000)/64

__global__ __launch_bounds__(256) void rope_kernel(const __half* __restrict__ qkv,
                                                   const int* __restrict__ positions,
                                                   __half* __restrict__ qh,
                                                   __half* __restrict__ kh) {
    int idx = blockIdx.x * blockDim.x + threadIdx.x;
    const int total = BB * SS * NH * HALF;
    if (idx >= total) return;
    int j = idx & 63;
    int h = (idx >> 6) & 31;
    int t = idx >> 11;
    int pos = positions[t];

    float inv_freq = __expf(-(float)j * LN1E4_OVER_64);
    float ang = (float)pos * inv_freq;
    float sn, cs;
    __sincosf(ang, &sn, &cs);

    size_t base = (size_t)t * THID + h * HD;
    size_t obase = (size_t)t * HID + h * HD;
    {
        float x1 = __half2float(qkv[base + j]);
        float x2 = __half2float(qkv[base + HALF + j]);
        qh[obase + j]        = __float2half((x1 * cs - x2 * sn) * SCALING);
        qh[obase + HALF + j] = __float2half((x2 * cs + x1 * sn) * SCALING);
    }
    {
        size_t kb = base + HID;
        float x1 = __half2float(qkv[kb + j]);
        float x2 = __half2float(qkv[kb + HALF + j]);
        kh[obase + j]        = __float2half(x1 * cs - x2 * sn);
        kh[obase + HALF + j] = __float2half(x2 * cs + x1 * sn);
    }
}

// ---------------------------------------------------------------------------
// Flash attention on HMMA. V read directly from fp16 qkv (stride THID).
// ---------------------------------------------------------------------------
#define FSM_Q 0
#define FSM_K 16384
#define FSM_V 32768
#define FLASH_DYN 49152

__global__ __launch_bounds__(128, 3) void flash_hmma(const __half* __restrict__ qh,
                                                     const __half* __restrict__ kh,
                                                     const __half* __restrict__ qkvh,
                                                     __half* __restrict__ ah) {
    const int qt = blockIdx.x;
    const int h  = blockIdx.y;
    const int b  = blockIdx.z;

    extern __shared__ char dsm[];
    const uint32_t sb = smem_u32(dsm);
    const int tid  = threadIdx.x;
    const int lane = tid & 31;
    const int wid  = tid >> 5;
    const int fr = lane >> 2;
    const int qq = lane & 3;

    const int a_r  = lane & 15;
    const int a_gh = lane >> 4;
    const int b_r  = (lane & 7) + ((lane >> 4) << 3);
    const int b_gh = (lane >> 3) & 1;
    const int vk   = (lane & 7) + (((lane >> 3) & 1) << 3);
    const int vg   = lane >> 4;

#pragma unroll
    for (int i = 0; i < 8; i++) {
        int idx = tid + i * 128;
        int row = idx >> 4, g = idx & 15;
        const __half* src = qh + ((size_t)(b * SS + qt * 64 + row) * HID + h * HD + g * 8);
        CP16(sb + FSM_Q + vswz(row, g), src);
    }
    CP_COMMIT();

    float o[16][4];
#pragma unroll
    for (int i = 0; i < 16; i++)
#pragma unroll
        for (int r = 0; r < 4; r++) o[i][r] = 0.f;
    float m0 = -1e30f, m1 = -1e30f, l0 = 0.f, l1 = 0.f;

    for (int j = 0; j <= qt; j++) {
#pragma unroll
        for (int i = 0; i < 8; i++) {
            int idx = tid + i * 128;
            int row = idx >> 4, g = idx & 15;
            int tok = b * SS + j * 64 + row;
            CP16(sb + FSM_K + vswz(row, g),
                 kh + ((size_t)tok * HID + h * HD + g * 8));
            CP16(sb + FSM_V + vswz(row, g),
                 qkvh + ((size_t)tok * THID + 2 * HID + h * HD + g * 8));
        }
        CP_COMMIT();
        CP_WAIT0();
        __syncthreads();

        float s[8][4];
#pragma unroll
        for (int nf = 0; nf < 8; nf++)
#pragma unroll
            for (int r = 0; r < 4; r++) s[nf][r] = 0.f;

#pragma unroll
        for (int ks = 0; ks < 8; ks++) {
            uint32_t aq[4];
            LDSM4(aq[0], aq[1], aq[2], aq[3],
                  sb + FSM_Q + vswz(wid * 16 + a_r, ks * 2 + a_gh));
#pragma unroll
            for (int np = 0; np < 4; np++) {
                uint32_t t0, t1, t2, t3;
                LDSM4(t0, t1, t2, t3, sb + FSM_K + vswz(np * 16 + b_r, ks * 2 + b_gh));
                MMA16816(s[np * 2],     aq, t0, t1);
                MMA16816(s[np * 2 + 1], aq, t2, t3);
            }
        }

        if (j == qt) {
            int row0 = wid * 16 + fr;
            int row1 = row0 + 8;
#pragma unroll
            for (int nf = 0; nf < 8; nf++) {
                int c0 = nf * 8 + qq * 2;
                if (c0 > row0)     s[nf][0] = -1e30f;
                if (c0 + 1 > row0) s[nf][1] = -1e30f;
                if (c0 > row1)     s[nf][2] = -1e30f;
                if (c0 + 1 > row1) s[nf][3] = -1e30f;
            }
        }

        float mx0 = -1e30f, mx1 = -1e30f;
#pragma unroll
        for (int nf = 0; nf < 8; nf++) {
            mx0 = fmaxf(mx0, fmaxf(s[nf][0], s[nf][1]));
            mx1 = fmaxf(mx1, fmaxf(s[nf][2], s[nf][3]));
        }
        mx0 = fmaxf(mx0, __shfl_xor_sync(0xffffffffu, mx0, 1));
        mx0 = fmaxf(mx0, __shfl_xor_sync(0xffffffffu, mx0, 2));
        mx1 = fmaxf(mx1, __shfl_xor_sync(0xffffffffu, mx1, 1));
        mx1 = fmaxf(mx1, __shfl_xor_sync(0xffffffffu, mx1, 2));

        float mn0 = fmaxf(m0, mx0), mn1 = fmaxf(m1, mx1);
        float f0 = __expf(m0 - mn0), f1 = __expf(m1 - mn1);
        m0 = mn0; m1 = mn1;

        uint32_t ph[8][2];
        float sum0 = 0.f, sum1 = 0.f;
#pragma unroll
        for (int nf = 0; nf < 8; nf++) {
            float p0 = __expf(s[nf][0] - m0);
            float p1 = __expf(s[nf][1] - m0);
            float p2 = __expf(s[nf][2] - m1);
            float p3 = __expf(s[nf][3] - m1);
            sum0 += p0 + p1; sum1 += p2 + p3;
            __half2 h01 = __floats2half2_rn(p0, p1);
            __half2 h23 = __floats2half2_rn(p2, p3);
            ph[nf][0] = *(uint32_t*)&h01;
            ph[nf][1] = *(uint32_t*)&h23;
        }
        sum0 += __shfl_xor_sync(0xffffffffu, sum0, 1);
        sum0 += __shfl_xor_sync(0xffffffffu, sum0, 2);
        sum1 += __shfl_xor_sync(0xffffffffu, sum1, 1);
        sum1 += __shfl_xor_sync(0xffffffffu, sum1, 2);
        l0 = l0 * f0 + sum0;
        l1 = l1 * f1 + sum1;

#pragma unroll
        for (int i = 0; i < 16; i++) {
            o[i][0] *= f0; o[i][1] *= f0;
            o[i][2] *= f1; o[i][3] *= f1;
        }

#pragma unroll
        for (int ks = 0; ks < 4; ks++) {
            uint32_t ap[4] = {ph[2 * ks][0], ph[2 * ks][1],
                              ph[2 * ks + 1][0], ph[2 * ks + 1][1]};
#pragma unroll
            for (int np = 0; np < 8; np++) {
                uint32_t t0, t1, t2, t3;
                LDSM4T(t0, t1, t2, t3, sb + FSM_V + vswz(ks * 16 + vk, np * 2 + vg));
                MMA16816(o[np * 2],     ap, t0, t1);
                MMA16816(o[np * 2 + 1], ap, t2, t3);
            }
        }
        __syncthreads();
    }

    float inv0 = 1.f / l0, inv1 = 1.f / l1;
    int row0 = b * SS + qt * 64 + wid * 16 + fr;
#pragma unroll
    for (int np = 0; np < 16; np++) {
        int col = h * HD + np * 8 + qq * 2;
        __half2 v0 = __floats2half2_rn(o[np][0] * inv0, o[np][1] * inv0);
        __half2 v1 = __floats2half2_rn(o[np][2] * inv1, o[np][3] * inv1);
        *(__half2*)(ah + (size_t)row0 * HID + col) = v0;
        *(__half2*)(ah + (size_t)(row0 + 8) * HID + col) = v1;
    }
}

// ---------------------------------------------------------------------------
extern "C" void kernel_launch(void* const* d_in, const int* in_sizes, int n_in,
                              void* d_out, int out_size) {
    const int*   positions = (const int*)  d_in[0];
    const float* hidden    = (const float*)d_in[1];
    const float* Wqkv      = (const float*)d_in[2];
    const float* Wo        = (const float*)d_in[3];
    float* out = (float*)d_out;

    __half *qkvh, *hh, *ah, *qh, *oh, *qhx, *khx;
    cudaGetSymbolAddress((void**)&qkvh, g_qkv_h);
    cudaGetSymbolAddress((void**)&hh, g_hid_h);
    cudaGetSymbolAddress((void**)&ah, g_attn_h);
    cudaGetSymbolAddress((void**)&qh, g_wqkv_h);
    cudaGetSymbolAddress((void**)&oh, g_wo_h);
    cudaGetSymbolAddress((void**)&qhx, g_q_h);
    cudaGetSymbolAddress((void**)&khx, g_k_h);

    int smCount = 148;
    cudaDeviceGetAttribute(&smCount, cudaDevAttrMultiProcessorCount, 0);
    const int pgrid = 2 * smCount;

    cudaFuncSetAttribute(gemm_mma_f16<__half>,
                         cudaFuncAttributeMaxDynamicSharedMemorySize, GEMM_DYN);
    cudaFuncSetAttribute(gemm_mma_f16<float>,
                         cudaFuncAttributeMaxDynamicSharedMemorySize, GEMM_DYN);
    cudaFuncSetAttribute(flash_hmma,
                         cudaFuncAttributeMaxDynamicSharedMemorySize, FLASH_DYN);

    {
        size_t n4 = (size_t)MTOK * HID / 4;
        convert_h<<<(unsigned)((n4 + 255) / 256), 256>>>(hidden, hh, n4);
    }
    transpose_h<<<dim3(THID / 32, HID / 32), 256>>>(Wqkv, qh, HID, THID);
    gemm_mma_f16<__half><<<pgrid, 256, GEMM_DYN>>>(hh, qh, qkvh, MTOK, THID, HID);
    {
        int total = BB * SS * NH * HALF;
        rope_kernel<<<(total + 255) / 256, 256>>>(qkvh, positions, qhx, khx);
    }
    flash_hmma<<<dim3(SS / 64, NH, BB), 128, FLASH_DYN>>>(qhx, khx, qkvh, ah);
    transpose_h<<<dim3(HID / 32, HID / 32), 256>>>(Wo, oh, HID, HID);
    gemm_mma_f16<float><<<pgrid, 256, GEMM_DYN>>>(ah, oh, out, MTOK, HID, HID);
}